// round 1
// baseline (speedup 1.0000x reference)
#include <cuda_runtime.h>
#include <math.h>

#define Bdim 32768
#define Ndim 2048
#define Hdim 512

// ---------------- scratch (device globals; no allocation allowed) ----------------
__device__ float g_mn[Ndim * Hdim];                     // normalized memory
__device__ float g_zinv[Bdim];                          // 1/||z_b||
__device__ float g_W[(size_t)Bdim * (size_t)Ndim];      // exp(sim)  (256MB)
__device__ float g_rowsum[Bdim];                        // sum_j exp(sim)
__device__ unsigned long long g_rowmax[Bdim];           // packed (keyenc(val)<<32 | idx)
__device__ unsigned int g_colmax[Ndim];                 // keyenc(float) atomicMax
__device__ float g_denom[Ndim];
__device__ float g_update[Ndim * Hdim];

// ---------------- helpers ----------------
__device__ __forceinline__ unsigned long long fma2(unsigned long long a, unsigned long long b, unsigned long long c) {
    unsigned long long d;
    asm("fma.rn.f32x2 %0, %1, %2, %3;" : "=l"(d) : "l"(a), "l"(b), "l"(c));
    return d;
}
__device__ __forceinline__ unsigned long long pack2(float x) {
    unsigned long long d;
    asm("mov.b64 %0, {%1, %2};" : "=l"(d) : "f"(x), "f"(x));
    return d;
}
__device__ __forceinline__ void unpack2(unsigned long long v, float& lo, float& hi) {
    asm("mov.b64 {%0, %1}, %2;" : "=f"(lo), "=f"(hi) : "l"(v));
}
// order-preserving float<->uint key
__device__ __forceinline__ unsigned int keyenc(float f) {
    unsigned int b = __float_as_uint(f);
    return (b & 0x80000000u) ? ~b : (b | 0x80000000u);
}
__device__ __forceinline__ float keydec(unsigned int v) {
    unsigned int b = (v & 0x80000000u) ? (v ^ 0x80000000u) : ~v;
    return __uint_as_float(b);
}

// ---------------- K0: zero scratch (must run every launch: graph is replayed) ----------------
__global__ void k_zero() {
    int i = blockIdx.x * blockDim.x + threadIdx.x;
    int stride = gridDim.x * blockDim.x;
    for (int j = i; j < Ndim * Hdim; j += stride) g_update[j] = 0.0f;
    for (int j = i; j < Bdim; j += stride) { g_rowsum[j] = 0.0f; g_rowmax[j] = 0ull; }
    for (int j = i; j < Ndim; j += stride) { g_colmax[j] = 0u; g_denom[j] = 0.0f; }
}

// ---------------- K norm: m_n = normalize(memory)  (one block per slot) ----------------
__global__ void k_norm_mem(const float* __restrict__ mem) {
    int i = blockIdx.x;
    __shared__ float red[256];
    const float* r = mem + (size_t)i * Hdim;
    float v0 = r[threadIdx.x];
    float v1 = r[threadIdx.x + 256];
    float ss = v0 * v0 + v1 * v1;
    red[threadIdx.x] = ss;
    __syncthreads();
    for (int s = 128; s > 0; s >>= 1) {
        if (threadIdx.x < s) red[threadIdx.x] += red[threadIdx.x + s];
        __syncthreads();
    }
    float inv = 1.0f / fmaxf(sqrtf(red[0]), 1e-12f);
    g_mn[(size_t)i * Hdim + threadIdx.x]       = v0 * inv;
    g_mn[(size_t)i * Hdim + threadIdx.x + 256] = v1 * inv;
}

// ---------------- K zinv: per-row 1/||z||  (one warp per row) ----------------
__global__ void k_zinv(const float* __restrict__ z) {
    int w = (blockIdx.x * blockDim.x + threadIdx.x) >> 5;
    int lane = threadIdx.x & 31;
    if (w >= Bdim) return;
    const float4* zr = (const float4*)(z + (size_t)w * Hdim);
    float ss = 0.0f;
#pragma unroll
    for (int h4 = 0; h4 < 4; h4++) {
        float4 v = zr[lane + 32 * h4];
        ss += v.x * v.x + v.y * v.y + v.z * v.z + v.w * v.w;
    }
#pragma unroll
    for (int o = 16; o; o >>= 1) ss += __shfl_down_sync(0xffffffffu, ss, o);
    if (lane == 0) g_zinv[w] = 1.0f / fmaxf(sqrtf(ss), 1e-12f);
}

// ---------------- GEMM1: W = exp(z_n @ m_n^T), rowsum, row argmax ----------------
__device__ __forceinline__ void gemm1_epi_row(
    const float* __restrict__ s, int rl, int m0, int n0, int tx,
    float s_sum[128][16], float s_val[128][16], int s_idx[128][16])
{
    float w[8];
    float sum = 0.0f, bv = -1e30f;
    int bi = 0;
#pragma unroll
    for (int j = 0; j < 8; j++) {
        w[j] = expf(s[j]);
        sum += w[j];
        if (s[j] > bv) { bv = s[j]; bi = n0 + (tx << 3) + j; }
    }
    size_t wb = (size_t)(m0 + rl) * Ndim + n0 + (tx << 3);
    *(float4*)&g_W[wb]     = make_float4(w[0], w[1], w[2], w[3]);
    *(float4*)&g_W[wb + 4] = make_float4(w[4], w[5], w[6], w[7]);
    s_sum[rl][tx] = sum;
    s_val[rl][tx] = bv;
    s_idx[rl][tx] = bi;
}

__global__ __launch_bounds__(256) void k_gemm1(const float* __restrict__ z) {
    __shared__ float As[16][128];
    __shared__ float Bs[16][128];
    __shared__ float s_sum[128][16];
    __shared__ float s_val[128][16];
    __shared__ int   s_idx[128][16];

    const int tid = threadIdx.x;
    const int tx = tid & 15, ty = tid >> 4;
    const int m0 = blockIdx.y << 7;
    const int n0 = blockIdx.x << 7;
    const int lrow = tid >> 1;
    const int lk = (tid & 1) << 3;

    const float za = g_zinv[m0 + lrow];
    const float* zA = z + (size_t)(m0 + lrow) * Hdim + lk;
    const float* mB = g_mn + (size_t)(n0 + lrow) * Hdim + lk;

    unsigned long long acc[4][8];
#pragma unroll
    for (int i = 0; i < 4; i++)
#pragma unroll
        for (int j = 0; j < 8; j++) acc[i][j] = 0ull;

    for (int k0 = 0; k0 < Hdim; k0 += 16) {
        float4 a0 = *(const float4*)(zA + k0);
        float4 a1 = *(const float4*)(zA + k0 + 4);
        float4 b0 = *(const float4*)(mB + k0);
        float4 b1 = *(const float4*)(mB + k0 + 4);
        As[lk + 0][lrow] = a0.x * za; As[lk + 1][lrow] = a0.y * za;
        As[lk + 2][lrow] = a0.z * za; As[lk + 3][lrow] = a0.w * za;
        As[lk + 4][lrow] = a1.x * za; As[lk + 5][lrow] = a1.y * za;
        As[lk + 6][lrow] = a1.z * za; As[lk + 7][lrow] = a1.w * za;
        Bs[lk + 0][lrow] = b0.x; Bs[lk + 1][lrow] = b0.y;
        Bs[lk + 2][lrow] = b0.z; Bs[lk + 3][lrow] = b0.w;
        Bs[lk + 4][lrow] = b1.x; Bs[lk + 5][lrow] = b1.y;
        Bs[lk + 6][lrow] = b1.z; Bs[lk + 7][lrow] = b1.w;
        __syncthreads();
#pragma unroll
        for (int k = 0; k < 16; k++) {
            const unsigned long long* ap = (const unsigned long long*)&As[k][ty << 3];
            unsigned long long a0p = ap[0], a1p = ap[1], a2p = ap[2], a3p = ap[3];
            float4 bv0 = *(const float4*)&Bs[k][tx << 3];
            float4 bv1 = *(const float4*)&Bs[k][(tx << 3) + 4];
            unsigned long long b2[8];
            b2[0] = pack2(bv0.x); b2[1] = pack2(bv0.y); b2[2] = pack2(bv0.z); b2[3] = pack2(bv0.w);
            b2[4] = pack2(bv1.x); b2[5] = pack2(bv1.y); b2[6] = pack2(bv1.z); b2[7] = pack2(bv1.w);
#pragma unroll
            for (int j = 0; j < 8; j++) {
                acc[0][j] = fma2(a0p, b2[j], acc[0][j]);
                acc[1][j] = fma2(a1p, b2[j], acc[1][j]);
                acc[2][j] = fma2(a2p, b2[j], acc[2][j]);
                acc[3][j] = fma2(a3p, b2[j], acc[3][j]);
            }
        }
        __syncthreads();
    }

    // epilogue: exp, store W, per-row partial sum + argmax into smem
#pragma unroll
    for (int i = 0; i < 4; i++) {
        float slo[8], shi[8];
#pragma unroll
        for (int j = 0; j < 8; j++) unpack2(acc[i][j], slo[j], shi[j]);
        gemm1_epi_row(slo, (ty << 3) + (i << 1) + 0, m0, n0, tx, s_sum, s_val, s_idx);
        gemm1_epi_row(shi, (ty << 3) + (i << 1) + 1, m0, n0, tx, s_sum, s_val, s_idx);
    }
    __syncthreads();
    if (tid < 128) {
        float sum = 0.0f, bv = -1e30f;
        int bi = 0;
#pragma unroll
        for (int t = 0; t < 16; t++) {
            sum += s_sum[tid][t];
            float v = s_val[tid][t];
            if (v > bv) { bv = v; bi = s_idx[tid][t]; }
        }
        atomicAdd(&g_rowsum[m0 + tid], sum);
        unsigned long long key = ((unsigned long long)keyenc(bv) << 32) | (unsigned int)bi;
        atomicMax(&g_rowmax[m0 + tid], key);
    }
}

// ---------------- GEMM2: z_hat = (W @ memory) / rowsum ----------------
__global__ __launch_bounds__(256) void k_gemm2(const float* __restrict__ mem, float* __restrict__ out) {
    __shared__ float As[16][128];
    __shared__ float Bs[16][128];

    const int tid = threadIdx.x;
    const int tx = tid & 15, ty = tid >> 4;
    const int m0 = blockIdx.y << 7;
    const int n0 = blockIdx.x << 7;
    const int lrow = tid >> 1;
    const int lk = (tid & 1) << 3;
    const int bk = tid >> 4;          // 0..15
    const int bn = (tid & 15) << 3;   // 0..120

    const float* wA = g_W + (size_t)(m0 + lrow) * Ndim + lk;

    unsigned long long acc[4][8];
#pragma unroll
    for (int i = 0; i < 4; i++)
#pragma unroll
        for (int j = 0; j < 8; j++) acc[i][j] = 0ull;

    for (int k0 = 0; k0 < Ndim; k0 += 16) {
        float4 a0 = *(const float4*)(wA + k0);
        float4 a1 = *(const float4*)(wA + k0 + 4);
        const float* mrow = mem + (size_t)(k0 + bk) * Hdim + n0 + bn;
        float4 b0 = *(const float4*)(mrow);
        float4 b1 = *(const float4*)(mrow + 4);
        As[lk + 0][lrow] = a0.x; As[lk + 1][lrow] = a0.y;
        As[lk + 2][lrow] = a0.z; As[lk + 3][lrow] = a0.w;
        As[lk + 4][lrow] = a1.x; As[lk + 5][lrow] = a1.y;
        As[lk + 6][lrow] = a1.z; As[lk + 7][lrow] = a1.w;
        *(float4*)&Bs[bk][bn]     = b0;
        *(float4*)&Bs[bk][bn + 4] = b1;
        __syncthreads();
#pragma unroll
        for (int k = 0; k < 16; k++) {
            const unsigned long long* ap = (const unsigned long long*)&As[k][ty << 3];
            unsigned long long a0p = ap[0], a1p = ap[1], a2p = ap[2], a3p = ap[3];
            float4 bv0 = *(const float4*)&Bs[k][tx << 3];
            float4 bv1 = *(const float4*)&Bs[k][(tx << 3) + 4];
            unsigned long long b2[8];
            b2[0] = pack2(bv0.x); b2[1] = pack2(bv0.y); b2[2] = pack2(bv0.z); b2[3] = pack2(bv0.w);
            b2[4] = pack2(bv1.x); b2[5] = pack2(bv1.y); b2[6] = pack2(bv1.z); b2[7] = pack2(bv1.w);
#pragma unroll
            for (int j = 0; j < 8; j++) {
                acc[0][j] = fma2(a0p, b2[j], acc[0][j]);
                acc[1][j] = fma2(a1p, b2[j], acc[1][j]);
                acc[2][j] = fma2(a2p, b2[j], acc[2][j]);
                acc[3][j] = fma2(a3p, b2[j], acc[3][j]);
            }
        }
        __syncthreads();
    }

#pragma unroll
    for (int i = 0; i < 4; i++) {
        float lo[8], hi[8];
#pragma unroll
        for (int j = 0; j < 8; j++) unpack2(acc[i][j], lo[j], hi[j]);
        int r0 = (ty << 3) + (i << 1);
        float inv0 = 1.0f / g_rowsum[m0 + r0];
        float inv1 = 1.0f / g_rowsum[m0 + r0 + 1];
        size_t o0 = (size_t)(m0 + r0) * Hdim + n0 + (tx << 3);
        size_t o1 = o0 + Hdim;
        *(float4*)&out[o0]     = make_float4(lo[0] * inv0, lo[1] * inv0, lo[2] * inv0, lo[3] * inv0);
        *(float4*)&out[o0 + 4] = make_float4(lo[4] * inv0, lo[5] * inv0, lo[6] * inv0, lo[7] * inv0);
        *(float4*)&out[o1]     = make_float4(hi[0] * inv1, hi[1] * inv1, hi[2] * inv1, hi[3] * inv1);
        *(float4*)&out[o1 + 4] = make_float4(hi[4] * inv1, hi[5] * inv1, hi[6] * inv1, hi[7] * inv1);
    }
}

// ---------------- K3: column max over argmax rows ----------------
__global__ void k_colmax() {
    int b = blockIdx.x * blockDim.x + threadIdx.x;
    if (b >= Bdim) return;
    unsigned long long key = g_rowmax[b];
    unsigned int vkey = (unsigned int)(key >> 32);
    int idx = (int)(key & 0xFFFFFFFFull);
    atomicMax(&g_colmax[idx], vkey);   // key space is order-preserving
}

// ---------------- K4: scatter  denom[i] += p,  update[i,:] += p * z[b,:]  (warp per row) ----------------
__global__ void k_scatter(const float* __restrict__ z) {
    int row = blockIdx.x * 8 + (threadIdx.x >> 5);
    int lane = threadIdx.x & 31;
    if (row >= Bdim) return;
    unsigned long long key = g_rowmax[row];
    int idx = (int)(key & 0xFFFFFFFFull);
    float val = keydec((unsigned int)(key >> 32));
    float cm = keydec(g_colmax[idx]);
    float p = expf(val - cm);
    if (lane == 0) atomicAdd(&g_denom[idx], p);
    const float* zr = z + (size_t)row * Hdim;
    float* up = g_update + (size_t)idx * Hdim;
#pragma unroll
    for (int h = 0; h < Hdim; h += 32) {
        atomicAdd(&up[h + lane], p * zr[h + lane]);
    }
}

// ---------------- K5: new_memory = normalize(memory + update/denom) or memory ----------------
__global__ void k_finalize(const float* __restrict__ mem, float* __restrict__ out) {
    int i = blockIdx.x;
    __shared__ float red[256];
    float d = g_denom[i];
    const float* mr = mem + (size_t)i * Hdim;
    float* o = out + (size_t)Bdim * Hdim + (size_t)i * Hdim;
    if (d > 0.0f) {
        float invd = 1.0f / d;
        float v0 = mr[threadIdx.x]       + g_update[(size_t)i * Hdim + threadIdx.x] * invd;
        float v1 = mr[threadIdx.x + 256] + g_update[(size_t)i * Hdim + threadIdx.x + 256] * invd;
        red[threadIdx.x] = v0 * v0 + v1 * v1;
        __syncthreads();
        for (int s = 128; s > 0; s >>= 1) {
            if (threadIdx.x < s) red[threadIdx.x] += red[threadIdx.x + s];
            __syncthreads();
        }
        float inv = 1.0f / fmaxf(sqrtf(red[0]), 1e-12f);
        o[threadIdx.x]       = v0 * inv;
        o[threadIdx.x + 256] = v1 * inv;
    } else {
        o[threadIdx.x]       = mr[threadIdx.x];
        o[threadIdx.x + 256] = mr[threadIdx.x + 256];
    }
}

// ---------------- launch ----------------
extern "C" void kernel_launch(void* const* d_in, const int* in_sizes, int n_in,
                              void* d_out, int out_size) {
    (void)in_sizes; (void)n_in; (void)out_size;
    const float* z   = (const float*)d_in[0];
    const float* mem = (const float*)d_in[1];
    float* out = (float*)d_out;

    k_zero<<<1024, 256>>>();
    k_norm_mem<<<Ndim, 256>>>(mem);
    k_zinv<<<(Bdim * 32) / 256, 256>>>(z);
    k_gemm1<<<dim3(Ndim / 128, Bdim / 128), 256>>>(z);
    k_gemm2<<<dim3(Hdim / 128, Bdim / 128), 256>>>(mem, out);
    k_colmax<<<Bdim / 256, 256>>>();
    k_scatter<<<Bdim / 8, 256>>>(z);
    k_finalize<<<Ndim, 256>>>(mem, out);
}

// round 3
// speedup vs baseline: 2.6498x; 2.6498x over previous
#include <cuda_runtime.h>
#include <cuda_bf16.h>
#include <math.h>
#include <stdint.h>

#define Bdim 32768
#define Ndim 2048
#define Hdim 512

// ---------------- scratch (device globals; no allocation allowed) ----------------
__device__ __align__(16) float g_mn[Ndim * Hdim];                 // normalized memory fp32
__device__ float g_zinv[Bdim];
__device__ __align__(16) __nv_bfloat16 g_zh[(size_t)Bdim * Hdim]; // normalized z hi
__device__ __align__(16) __nv_bfloat16 g_zl[(size_t)Bdim * Hdim]; // normalized z lo
__device__ __align__(16) __nv_bfloat16 g_mh[Ndim * Hdim];         // normalized mem hi
__device__ __align__(16) __nv_bfloat16 g_ml[Ndim * Hdim];         // normalized mem lo
__device__ __align__(16) __nv_bfloat16 g_mth[Hdim * Ndim];        // mem^T hi (raw mem)
__device__ __align__(16) __nv_bfloat16 g_mtl[Hdim * Ndim];        // mem^T lo
__device__ __align__(16) __nv_bfloat16 g_Wh[(size_t)Bdim * Ndim]; // exp(sim) hi
__device__ __align__(16) __nv_bfloat16 g_Wl[(size_t)Bdim * Ndim]; // exp(sim) lo
__device__ float g_rowsum[Bdim];
__device__ unsigned long long g_rowmax[Bdim];                     // (keyenc(val)<<32)|idx
__device__ unsigned int g_colmax[Ndim];
__device__ float g_denom[Ndim];
__device__ float g_update[Ndim * Hdim];

// ---------------- helpers ----------------
__device__ __forceinline__ unsigned int keyenc(float f) {
    unsigned int b = __float_as_uint(f);
    return (b & 0x80000000u) ? ~b : (b | 0x80000000u);
}
__device__ __forceinline__ float keydec(unsigned int v) {
    unsigned int b = (v & 0x80000000u) ? (v ^ 0x80000000u) : ~v;
    return __uint_as_float(b);
}
__device__ __forceinline__ void bsplit(float x, __nv_bfloat16& h, __nv_bfloat16& l) {
    h = __float2bfloat16(x);
    l = __float2bfloat16(x - __bfloat162float(h));
}
__device__ __forceinline__ unsigned int pkb(__nv_bfloat16 a, __nv_bfloat16 b) {
    return ((unsigned int)__bfloat16_as_ushort(b) << 16) | (unsigned int)__bfloat16_as_ushort(a);
}
__device__ __forceinline__ uint32_t smem_u32(const void* p) {
    uint32_t a;
    asm("{ .reg .u64 t; cvta.to.shared.u64 t, %1; cvt.u32.u64 %0, t; }" : "=r"(a) : "l"(p));
    return a;
}
__device__ __forceinline__ int swz(int off) { return off ^ ((off >> 3) & 0x70); }

__device__ __forceinline__ void cp16(uint32_t d, const void* s) {
    asm volatile("cp.async.cg.shared.global [%0], [%1], 16;" :: "r"(d), "l"(s));
}
#define CP_COMMIT() asm volatile("cp.async.commit_group;" ::: "memory")
#define CP_WAIT(n)  asm volatile("cp.async.wait_group %0;" :: "n"(n) : "memory")

__device__ __forceinline__ void ldsm4(uint32_t* r, uint32_t a) {
    asm volatile("ldmatrix.sync.aligned.m8n8.x4.shared.b16 {%0,%1,%2,%3}, [%4];"
        : "=r"(r[0]), "=r"(r[1]), "=r"(r[2]), "=r"(r[3]) : "r"(a));
}
__device__ __forceinline__ void mma16816(float* c, const uint32_t* a, const uint32_t* b) {
    asm volatile(
        "mma.sync.aligned.m16n8k16.row.col.f32.bf16.bf16.f32 "
        "{%0,%1,%2,%3},{%4,%5,%6,%7},{%8,%9},{%0,%1,%2,%3};"
        : "+f"(c[0]), "+f"(c[1]), "+f"(c[2]), "+f"(c[3])
        : "r"(a[0]), "r"(a[1]), "r"(a[2]), "r"(a[3]), "r"(b[0]), "r"(b[1]));
}

// ---------------- K0: zero scratch ----------------
__global__ void k_zero() {
    int i = blockIdx.x * blockDim.x + threadIdx.x;
    int stride = gridDim.x * blockDim.x;
    for (int j = i; j < Ndim * Hdim; j += stride) g_update[j] = 0.0f;
    for (int j = i; j < Bdim; j += stride) { g_rowsum[j] = 0.0f; g_rowmax[j] = 0ull; }
    for (int j = i; j < Ndim; j += stride) { g_colmax[j] = 0u; g_denom[j] = 0.0f; }
}

// ---------------- normalize memory -> g_mn fp32 + bf16 splits ----------------
__global__ void k_norm_mem(const float* __restrict__ mem) {
    int i = blockIdx.x;
    __shared__ float red[256];
    const float* r = mem + (size_t)i * Hdim;
    float v0 = r[threadIdx.x];
    float v1 = r[threadIdx.x + 256];
    red[threadIdx.x] = v0 * v0 + v1 * v1;
    __syncthreads();
    for (int s = 128; s > 0; s >>= 1) {
        if (threadIdx.x < s) red[threadIdx.x] += red[threadIdx.x + s];
        __syncthreads();
    }
    float inv = 1.0f / fmaxf(sqrtf(red[0]), 1e-12f);
    float n0 = v0 * inv, n1 = v1 * inv;
    size_t b = (size_t)i * Hdim + threadIdx.x;
    g_mn[b] = n0; g_mn[b + 256] = n1;
    __nv_bfloat16 h, l;
    bsplit(n0, h, l); g_mh[b] = h; g_ml[b] = l;
    bsplit(n1, h, l); g_mh[b + 256] = h; g_ml[b + 256] = l;
}

// ---------------- normalize z -> zinv + bf16 splits ----------------
__global__ void k_zsplit(const float* __restrict__ z) {
    int b = blockIdx.x;
    __shared__ float red[256];
    const float* r = z + (size_t)b * Hdim;
    float v0 = r[threadIdx.x];
    float v1 = r[threadIdx.x + 256];
    red[threadIdx.x] = v0 * v0 + v1 * v1;
    __syncthreads();
    for (int s = 128; s > 0; s >>= 1) {
        if (threadIdx.x < s) red[threadIdx.x] += red[threadIdx.x + s];
        __syncthreads();
    }
    float inv = 1.0f / fmaxf(sqrtf(red[0]), 1e-12f);
    if (threadIdx.x == 0) g_zinv[b] = inv;
    size_t o = (size_t)b * Hdim + threadIdx.x;
    __nv_bfloat16 h, l;
    bsplit(v0 * inv, h, l); g_zh[o] = h; g_zl[o] = l;
    bsplit(v1 * inv, h, l); g_zh[o + 256] = h; g_zl[o + 256] = l;
}

// ---------------- transpose raw mem -> memT bf16 splits ----------------
__global__ void k_memT(const float* __restrict__ mem) {
    __shared__ float t[32][33];
    int h0 = blockIdx.x * 32, n0 = blockIdx.y * 32;
    int tx = threadIdx.x, ty = threadIdx.y;
#pragma unroll
    for (int i = 0; i < 4; i++)
        t[ty + 8 * i][tx] = mem[(size_t)(n0 + ty + 8 * i) * Hdim + h0 + tx];
    __syncthreads();
#pragma unroll
    for (int i = 0; i < 4; i++) {
        int h = h0 + ty + 8 * i, n = n0 + tx;
        float v = t[tx][ty + 8 * i];
        __nv_bfloat16 hh, ll;
        bsplit(v, hh, ll);
        g_mth[(size_t)h * Ndim + n] = hh;
        g_mtl[(size_t)h * Ndim + n] = ll;
    }
}

// ---------------- mma.sync GEMM (128x128 block, BK=64, 2-stage cp.async) ----------------
// PHASE 1: sim = zn @ mn^T  -> exp, W splits, rowsum, rowmax
// PHASE 2: zhat = W @ memT^T / rowsum -> out
template <int KTOT, int PHASE>
__global__ __launch_bounds__(256, 1)
void k_gemm_mma(float* __restrict__ out) {
    constexpr int NC = KTOT / 64;
    constexpr int STAGE = 65536;              // 4 operand tiles x 16KB
    extern __shared__ __align__(128) char smraw[];
    const uint32_t smb = smem_u32(smraw);

    const int tid = threadIdx.x;
    const int lane = tid & 31;
    const int w = tid >> 5;
    const int wm = (w & 3) << 5;              // warp row base in tile (0..96)
    const int wn = (w >> 2) << 6;             // warp col base in tile (0/64)
    const int m0 = blockIdx.y << 7;
    const int n0 = blockIdx.x << 7;

    const __nv_bfloat16 *Ah, *Al, *Bh, *Bl;
    if (PHASE == 1) { Ah = g_zh; Al = g_zl; Bh = g_mh;  Bl = g_ml;  }
    else            { Ah = g_Wh; Al = g_Wl; Bh = g_mth; Bl = g_mtl; }

    // cp.async granule mapping: 4 per operand per thread
    int grow[4], gcol[4], gswo[4];
#pragma unroll
    for (int q = 0; q < 4; q++) {
        int id = tid + (q << 8);
        grow[q] = id >> 3;
        gcol[q] = (id & 7) << 3;
        gswo[q] = swz(grow[q] * 128 + ((id & 7) << 4));
    }

    float acc[2][8][4];
#pragma unroll
    for (int i = 0; i < 2; i++)
#pragma unroll
        for (int j = 0; j < 8; j++)
#pragma unroll
            for (int q = 0; q < 4; q++) acc[i][j][q] = 0.0f;

#define LOAD_STAGE(c, s) do {                                                        \
    uint32_t sb_ = smb + (s) * STAGE;                                                \
    size_t k0_ = (size_t)((c) << 6);                                                 \
    _Pragma("unroll")                                                                \
    for (int q = 0; q < 4; q++) {                                                    \
        size_t ao_ = (size_t)(m0 + grow[q]) * KTOT + k0_ + gcol[q];                  \
        size_t bo_ = (size_t)(n0 + grow[q]) * KTOT + k0_ + gcol[q];                  \
        cp16(sb_ + gswo[q],         Ah + ao_);                                       \
        cp16(sb_ + 16384 + gswo[q], Al + ao_);                                       \
        cp16(sb_ + 32768 + gswo[q], Bh + bo_);                                       \
        cp16(sb_ + 49152 + gswo[q], Bl + bo_);                                       \
    }                                                                                \
    CP_COMMIT();                                                                     \
} while (0)

    LOAD_STAGE(0, 0);

    for (int c = 0; c < NC; c++) {
        if (c + 1 < NC) {
            LOAD_STAGE(c + 1, (c + 1) & 1);
            CP_WAIT(1);
        } else {
            CP_WAIT(0);
        }
        __syncthreads();

        const uint32_t sA_h = smb + (c & 1) * STAGE;
        const uint32_t sA_l = sA_h + 16384;
        const uint32_t sB_h = sA_h + 32768;
        const uint32_t sB_l = sA_h + 49152;

#pragma unroll
        for (int k16 = 0; k16 < 4; k16++) {
            uint32_t ah[2][4], al_[2][4];
#pragma unroll
            for (int mi = 0; mi < 2; mi++) {
                int rA = wm + (mi << 4) + (lane & 15);
                int cA = (k16 << 1) + (lane >> 4);
                uint32_t off = rA * 128 + ((cA ^ (rA & 7)) << 4);
                ldsm4(ah[mi],  sA_h + off);
                ldsm4(al_[mi], sA_l + off);
            }
            uint32_t bh[4][4], bl_[4][4];
#pragma unroll
            for (int ng = 0; ng < 4; ng++) {
                int rB = wn + (ng << 4) + (lane & 7) + ((lane & 16) >> 1);
                int cB = (k16 << 1) + ((lane >> 3) & 1);
                uint32_t off = rB * 128 + ((cB ^ (rB & 7)) << 4);
                ldsm4(bh[ng],  sB_h + off);
                ldsm4(bl_[ng], sB_l + off);
            }
#pragma unroll
            for (int mi = 0; mi < 2; mi++)
#pragma unroll
                for (int ng = 0; ng < 4; ng++)
#pragma unroll
                    for (int s2 = 0; s2 < 2; s2++) {
                        float* cc = acc[mi][ng * 2 + s2];
                        mma16816(cc, ah[mi],  &bh[ng][s2 * 2]);
                        mma16816(cc, al_[mi], &bh[ng][s2 * 2]);
                        mma16816(cc, ah[mi],  &bl_[ng][s2 * 2]);
                    }
        }
        __syncthreads();
    }
#undef LOAD_STAGE

    // ---------------- epilogue ----------------
    const int rq = lane >> 2;                 // 0..7 row within octet
    const int cq = (lane & 3) << 1;           // 0..6 col pair base

    if (PHASE == 1) {
        float rs[2][2] = {{0.f, 0.f}, {0.f, 0.f}};
        float bv[2][2] = {{-1e30f, -1e30f}, {-1e30f, -1e30f}};
        int   bi[2][2] = {{0, 0}, {0, 0}};
#pragma unroll
        for (int mi = 0; mi < 2; mi++)
#pragma unroll
            for (int ni = 0; ni < 8; ni++) {
                float* cc = acc[mi][ni];
                int colb = n0 + wn + ni * 8 + cq;
#pragma unroll
                for (int h = 0; h < 2; h++) {
                    float v0 = cc[h * 2], v1 = cc[h * 2 + 1];
                    float e0 = expf(v0), e1 = expf(v1);
                    rs[mi][h] += e0 + e1;
                    if (v0 > bv[mi][h]) { bv[mi][h] = v0; bi[mi][h] = colb; }
                    if (v1 > bv[mi][h]) { bv[mi][h] = v1; bi[mi][h] = colb + 1; }
                    __nv_bfloat16 h0, l0, h1, l1;
                    bsplit(e0, h0, l0); bsplit(e1, h1, l1);
                    int row = m0 + wm + mi * 16 + rq + h * 8;
                    size_t o = (size_t)row * Ndim + colb;
                    *(uint32_t*)&g_Wh[o] = pkb(h0, h1);
                    *(uint32_t*)&g_Wl[o] = pkb(l0, l1);
                }
            }
        // quad reduce (lanes sharing a row differ only in lane&3)
#pragma unroll
        for (int mi = 0; mi < 2; mi++)
#pragma unroll
            for (int h = 0; h < 2; h++) {
#pragma unroll
                for (int o = 1; o <= 2; o <<= 1) {
                    rs[mi][h] += __shfl_xor_sync(0xffffffffu, rs[mi][h], o);
                    float ov = __shfl_xor_sync(0xffffffffu, bv[mi][h], o);
                    int   oi = __shfl_xor_sync(0xffffffffu, bi[mi][h], o);
                    if (ov > bv[mi][h]) { bv[mi][h] = ov; bi[mi][h] = oi; }
                }
                if ((lane & 3) == 0) {
                    int row = m0 + wm + mi * 16 + rq + h * 8;
                    atomicAdd(&g_rowsum[row], rs[mi][h]);
                    unsigned long long key =
                        ((unsigned long long)keyenc(bv[mi][h]) << 32) | (unsigned int)bi[mi][h];
                    atomicMax(&g_rowmax[row], key);
                }
            }
    } else {
#pragma unroll
        for (int mi = 0; mi < 2; mi++)
#pragma unroll
            for (int h = 0; h < 2; h++) {
                int row = m0 + wm + mi * 16 + rq + h * 8;
                float inv = 1.0f / g_rowsum[row];
#pragma unroll
                for (int ni = 0; ni < 8; ni++) {
                    float* cc = acc[mi][ni];
                    int col = n0 + wn + ni * 8 + cq;
                    float2 v = make_float2(cc[h * 2] * inv, cc[h * 2 + 1] * inv);
                    *(float2*)&out[(size_t)row * Hdim + col] = v;
                }
            }
    }
}

// ---------------- argmax correction: exact fp32 recheck for near-ties ----------------
__global__ void k_argmax_fix(const float* __restrict__ z) {
    const int wid = threadIdx.x >> 5, lane = threadIdx.x & 31;
    const int row = blockIdx.x * 8 + wid;
    __shared__ int s_cnt[8];
    __shared__ int s_cand[8][8];

    const __nv_bfloat16* wh = g_Wh + (size_t)row * Ndim;
    const __nv_bfloat16* wl = g_Wl + (size_t)row * Ndim;

    float a1 = -1e30f, a2 = -1e30f;
    for (int t = 0; t < Ndim / 32; t++) {
        int j = t * 32 + lane;
        float wv = __bfloat162float(wh[j]) + __bfloat162float(wl[j]);
        if (wv > a1) { a2 = a1; a1 = wv; }
        else if (wv > a2) { a2 = wv; }
    }
#pragma unroll
    for (int o = 16; o; o >>= 1) {
        float b1 = __shfl_down_sync(0xffffffffu, a1, o);
        float b2 = __shfl_down_sync(0xffffffffu, a2, o);
        if (b1 > a1) { a2 = fmaxf(a1, b2); a1 = b1; }
        else if (b1 > a2) { a2 = b1; }
    }
    a1 = __shfl_sync(0xffffffffu, a1, 0);
    a2 = __shfl_sync(0xffffffffu, a2, 0);

    float thr = a1 * (1.0f - 1e-4f);
    if (a2 < thr) return;   // unambiguous: keep gemm1 argmax

    if (lane == 0) s_cnt[wid] = 0;
    __syncwarp();
    for (int t = 0; t < Ndim / 32; t++) {
        int j = t * 32 + lane;
        float wv = __bfloat162float(wh[j]) + __bfloat162float(wl[j]);
        if (wv >= thr) {
            int p = atomicAdd(&s_cnt[wid], 1);
            if (p < 8) s_cand[wid][p] = j;
        }
    }
    __syncwarp();
    int cnt = min(s_cnt[wid], 8);

    float zin = g_zinv[row];
    const float* zr = z + (size_t)row * Hdim;
    float best = -1e30f;
    int bi = -1;
    for (int c = 0; c < cnt; c++) {
        int j = s_cand[wid][c];
        const float* mr = g_mn + (size_t)j * Hdim;
        float s = 0.0f;
        for (int t = 0; t < 16; t++) {
            int h = t * 32 + lane;
            s += zr[h] * zin * mr[h];
        }
#pragma unroll
        for (int o = 16; o; o >>= 1) s += __shfl_down_sync(0xffffffffu, s, o);
        s = __shfl_sync(0xffffffffu, s, 0);
        if (s > best) { best = s; bi = j; }
    }
    if (lane == 0)
        g_rowmax[row] = ((unsigned long long)keyenc(best) << 32) | (unsigned int)bi;
}

// ---------------- column max over argmax rows ----------------
__global__ void k_colmax() {
    int b = blockIdx.x * blockDim.x + threadIdx.x;
    if (b >= Bdim) return;
    unsigned long long key = g_rowmax[b];
    atomicMax(&g_colmax[key & 0xFFFFFFFFull], (unsigned int)(key >> 32));
}

// ---------------- scatter update ----------------
__global__ void k_scatter(const float* __restrict__ z) {
    int row = blockIdx.x * 8 + (threadIdx.x >> 5);
    int lane = threadIdx.x & 31;
    if (row >= Bdim) return;
    unsigned long long key = g_rowmax[row];
    int idx = (int)(key & 0xFFFFFFFFull);
    float val = keydec((unsigned int)(key >> 32));
    float cm = keydec(g_colmax[idx]);
    float p = expf(val - cm);
    if (lane == 0) atomicAdd(&g_denom[idx], p);
    const float* zr = z + (size_t)row * Hdim;
    float* up = g_update + (size_t)idx * Hdim;
#pragma unroll
    for (int h = 0; h < Hdim; h += 32)
        atomicAdd(&up[h + lane], p * zr[h + lane]);
}

// ---------------- finalize new_memory ----------------
__global__ void k_finalize(const float* __restrict__ mem, float* __restrict__ out) {
    int i = blockIdx.x;
    __shared__ float red[256];
    float d = g_denom[i];
    const float* mr = mem + (size_t)i * Hdim;
    float* o = out + (size_t)Bdim * Hdim + (size_t)i * Hdim;
    if (d > 0.0f) {
        float invd = 1.0f / d;
        float v0 = mr[threadIdx.x]       + g_update[(size_t)i * Hdim + threadIdx.x] * invd;
        float v1 = mr[threadIdx.x + 256] + g_update[(size_t)i * Hdim + threadIdx.x + 256] * invd;
        red[threadIdx.x] = v0 * v0 + v1 * v1;
        __syncthreads();
        for (int s = 128; s > 0; s >>= 1) {
            if (threadIdx.x < s) red[threadIdx.x] += red[threadIdx.x + s];
            __syncthreads();
        }
        float inv = 1.0f / fmaxf(sqrtf(red[0]), 1e-12f);
        o[threadIdx.x]       = v0 * inv;
        o[threadIdx.x + 256] = v1 * inv;
    } else {
        o[threadIdx.x]       = mr[threadIdx.x];
        o[threadIdx.x + 256] = mr[threadIdx.x + 256];
    }
}

// ---------------- launch ----------------
extern "C" void kernel_launch(void* const* d_in, const int* in_sizes, int n_in,
                              void* d_out, int out_size) {
    (void)in_sizes; (void)n_in; (void)out_size;
    const float* z   = (const float*)d_in[0];
    const float* mem = (const float*)d_in[1];
    float* out = (float*)d_out;

    const int DSMEM = 2 * 65536;   // 128KB
    cudaFuncSetAttribute(k_gemm_mma<Hdim, 1>, cudaFuncAttributeMaxDynamicSharedMemorySize, DSMEM);
    cudaFuncSetAttribute(k_gemm_mma<Ndim, 2>, cudaFuncAttributeMaxDynamicSharedMemorySize, DSMEM);

    k_zero<<<1024, 256>>>();
    k_norm_mem<<<Ndim, 256>>>(mem);
    k_zsplit<<<Bdim, 256>>>(z);
    k_memT<<<dim3(Hdim / 32, Ndim / 32), dim3(32, 8)>>>(mem);
    k_gemm_mma<Hdim, 1><<<dim3(Ndim / 128, Bdim / 128), 256, DSMEM>>>(nullptr);
    k_argmax_fix<<<Bdim / 8, 256>>>(z);
    k_gemm_mma<Ndim, 2><<<dim3(Hdim / 128, Bdim / 128), 256, DSMEM>>>(out);
    k_colmax<<<Bdim / 256, 256>>>();
    k_scatter<<<Bdim / 8, 256>>>(z);
    k_finalize<<<Ndim, 256>>>(mem, out);
}

// round 4
// speedup vs baseline: 3.9177x; 1.4785x over previous
#include <cuda_runtime.h>
#include <cuda_fp16.h>
#include <math.h>
#include <stdint.h>

#define Bdim 32768
#define Ndim 2048
#define Hdim 512

// ---------------- scratch (device globals; no allocation allowed) ----------------
__device__ __align__(16) float g_mn[Ndim * Hdim];            // normalized memory fp32
__device__ float g_zinv[Bdim];
__device__ __align__(16) __half g_zh[(size_t)Bdim * Hdim];   // normalized z fp16
__device__ __align__(16) __half g_mh[Ndim * Hdim];           // normalized mem fp16
__device__ __align__(16) __half g_mth[Hdim * Ndim];          // mem^T fp16 (raw mem)
__device__ __align__(16) __half g_Wh[(size_t)Bdim * Ndim];   // exp(sim) hi
__device__ __align__(16) __half g_Wl[(size_t)Bdim * Ndim];   // exp(sim) lo
__device__ float g_rowsum[Bdim];
__device__ unsigned long long g_rowmax[Bdim];                // (keyenc(val)<<32)|idx
__device__ unsigned int g_colmax[Ndim];
__device__ float g_denom[Ndim];
__device__ float g_update[Ndim * Hdim];

// ---------------- helpers ----------------
__device__ __forceinline__ unsigned int keyenc(float f) {
    unsigned int b = __float_as_uint(f);
    return (b & 0x80000000u) ? ~b : (b | 0x80000000u);
}
__device__ __forceinline__ float keydec(unsigned int v) {
    unsigned int b = (v & 0x80000000u) ? (v ^ 0x80000000u) : ~v;
    return __uint_as_float(b);
}
__device__ __forceinline__ void hsplit(float x, __half& h, __half& l) {
    h = __float2half_rn(x);
    l = __float2half_rn(x - __half2float(h));
}
__device__ __forceinline__ unsigned int pkh(__half a, __half b) {
    return ((unsigned int)__half_as_ushort(b) << 16) | (unsigned int)__half_as_ushort(a);
}
__device__ __forceinline__ uint32_t smem_u32(const void* p) {
    uint32_t a;
    asm("{ .reg .u64 t; cvta.to.shared.u64 t, %1; cvt.u32.u64 %0, t; }" : "=r"(a) : "l"(p));
    return a;
}
__device__ __forceinline__ int swz(int off) { return off ^ ((off >> 3) & 0x70); }

__device__ __forceinline__ void cp16(uint32_t d, const void* s) {
    asm volatile("cp.async.cg.shared.global [%0], [%1], 16;" :: "r"(d), "l"(s));
}
#define CP_COMMIT() asm volatile("cp.async.commit_group;" ::: "memory")
#define CP_WAIT(n)  asm volatile("cp.async.wait_group %0;" :: "n"(n) : "memory")

__device__ __forceinline__ void ldsm4(uint32_t* r, uint32_t a) {
    asm volatile("ldmatrix.sync.aligned.m8n8.x4.shared.b16 {%0,%1,%2,%3}, [%4];"
        : "=r"(r[0]), "=r"(r[1]), "=r"(r[2]), "=r"(r[3]) : "r"(a));
}
__device__ __forceinline__ void mma16816(float* c, const uint32_t* a, const uint32_t* b) {
    asm volatile(
        "mma.sync.aligned.m16n8k16.row.col.f32.f16.f16.f32 "
        "{%0,%1,%2,%3},{%4,%5,%6,%7},{%8,%9},{%0,%1,%2,%3};"
        : "+f"(c[0]), "+f"(c[1]), "+f"(c[2]), "+f"(c[3])
        : "r"(a[0]), "r"(a[1]), "r"(a[2]), "r"(a[3]), "r"(b[0]), "r"(b[1]));
}

// ---------------- K0: zero scratch ----------------
__global__ void k_zero() {
    int i = blockIdx.x * blockDim.x + threadIdx.x;
    int stride = gridDim.x * blockDim.x;
    for (int j = i; j < Ndim * Hdim; j += stride) g_update[j] = 0.0f;
    for (int j = i; j < Bdim; j += stride) { g_rowsum[j] = 0.0f; g_rowmax[j] = 0ull; }
    for (int j = i; j < Ndim; j += stride) { g_colmax[j] = 0u; g_denom[j] = 0.0f; }
}

// ---------------- normalize memory -> g_mn fp32 + fp16 ----------------
__global__ void k_norm_mem(const float* __restrict__ mem) {
    int i = blockIdx.x;
    __shared__ float red[256];
    const float* r = mem + (size_t)i * Hdim;
    float v0 = r[threadIdx.x];
    float v1 = r[threadIdx.x + 256];
    red[threadIdx.x] = v0 * v0 + v1 * v1;
    __syncthreads();
    for (int s = 128; s > 0; s >>= 1) {
        if (threadIdx.x < s) red[threadIdx.x] += red[threadIdx.x + s];
        __syncthreads();
    }
    float inv = 1.0f / fmaxf(sqrtf(red[0]), 1e-12f);
    float n0 = v0 * inv, n1 = v1 * inv;
    size_t b = (size_t)i * Hdim + threadIdx.x;
    g_mn[b] = n0; g_mn[b + 256] = n1;
    g_mh[b] = __float2half_rn(n0);
    g_mh[b + 256] = __float2half_rn(n1);
}

// ---------------- normalize z -> zinv + fp16 ----------------
__global__ void k_zsplit(const float* __restrict__ z) {
    int b = blockIdx.x;
    __shared__ float red[256];
    const float* r = z + (size_t)b * Hdim;
    float v0 = r[threadIdx.x];
    float v1 = r[threadIdx.x + 256];
    red[threadIdx.x] = v0 * v0 + v1 * v1;
    __syncthreads();
    for (int s = 128; s > 0; s >>= 1) {
        if (threadIdx.x < s) red[threadIdx.x] += red[threadIdx.x + s];
        __syncthreads();
    }
    float inv = 1.0f / fmaxf(sqrtf(red[0]), 1e-12f);
    if (threadIdx.x == 0) g_zinv[b] = inv;
    size_t o = (size_t)b * Hdim + threadIdx.x;
    g_zh[o] = __float2half_rn(v0 * inv);
    g_zh[o + 256] = __float2half_rn(v1 * inv);
}

// ---------------- transpose raw mem -> memT fp16 ----------------
__global__ void k_memT(const float* __restrict__ mem) {
    __shared__ float t[32][33];
    int h0 = blockIdx.x * 32, n0 = blockIdx.y * 32;
    int tx = threadIdx.x, ty = threadIdx.y;
#pragma unroll
    for (int i = 0; i < 4; i++)
        t[ty + 8 * i][tx] = mem[(size_t)(n0 + ty + 8 * i) * Hdim + h0 + tx];
    __syncthreads();
#pragma unroll
    for (int i = 0; i < 4; i++) {
        int h = h0 + ty + 8 * i, n = n0 + tx;
        g_mth[(size_t)h * Ndim + n] = __float2half_rn(t[tx][ty + 8 * i]);
    }
}

// ---------------- mma.sync GEMM (128x128 block, BK=64, 3-stage cp.async) ----------------
// PHASE 1 (NSA=1): sim = zh @ mh^T -> exp, W hi/lo, rowsum, rowmax
// PHASE 2 (NSA=2): zhat = (Wh+Wl) @ mth^T / rowsum -> out
template <int KTOT, int PHASE>
__global__ __launch_bounds__(256, 1)
void k_gemm_mma(float* __restrict__ out) {
    constexpr int NSA = (PHASE == 1) ? 1 : 2;
    constexpr int NC = KTOT / 64;
    constexpr int STAGE = (NSA + 1) * 16384;
    extern __shared__ __align__(128) char smraw[];
    const uint32_t smb = smem_u32(smraw);

    const int tid = threadIdx.x;
    const int lane = tid & 31;
    const int w = tid >> 5;
    const int wm = (w & 3) << 5;              // warp row base (0..96)
    const int wn = (w >> 2) << 6;             // warp col base (0/64)
    const int m0 = blockIdx.y << 7;
    const int n0 = blockIdx.x << 7;

    const __half *Ah, *Al, *Bh;
    if (PHASE == 1) { Ah = g_zh; Al = g_zh;  Bh = g_mh;  }
    else            { Ah = g_Wh; Al = g_Wl;  Bh = g_mth; }

    // cp.async granule mapping: 4 per operand-split per thread
    int grow[4], gcol[4], gswo[4];
#pragma unroll
    for (int q = 0; q < 4; q++) {
        int id = tid + (q << 8);
        grow[q] = id >> 3;
        gcol[q] = (id & 7) << 3;
        gswo[q] = swz(grow[q] * 128 + ((id & 7) << 4));
    }

    float acc[2][8][4];
#pragma unroll
    for (int i = 0; i < 2; i++)
#pragma unroll
        for (int j = 0; j < 8; j++)
#pragma unroll
            for (int q = 0; q < 4; q++) acc[i][j][q] = 0.0f;

#define LOAD_STAGE(c, s) do {                                                        \
    uint32_t sb_ = smb + (s) * STAGE;                                                \
    size_t k0_ = (size_t)((c) << 6);                                                 \
    _Pragma("unroll")                                                                \
    for (int q = 0; q < 4; q++) {                                                    \
        size_t ao_ = (size_t)(m0 + grow[q]) * KTOT + k0_ + gcol[q];                  \
        size_t bo_ = (size_t)(n0 + grow[q]) * KTOT + k0_ + gcol[q];                  \
        cp16(sb_ + gswo[q], Ah + ao_);                                               \
        if (NSA == 2) cp16(sb_ + 16384 + gswo[q], Al + ao_);                         \
        cp16(sb_ + NSA * 16384 + gswo[q], Bh + bo_);                                 \
    }                                                                                \
    CP_COMMIT();                                                                     \
} while (0)

    LOAD_STAGE(0, 0);
    if (NC > 1) LOAD_STAGE(1, 1); else CP_COMMIT();

    int st = 0;      // stage of chunk c
    for (int c = 0; c < NC; c++) {
        int pf = c + 2;
        int pst = st + 2; if (pst >= 3) pst -= 3;
        if (pf < NC) { LOAD_STAGE(pf, pst); } else { CP_COMMIT(); }
        CP_WAIT(2);
        __syncthreads();

        const uint32_t sA_h = smb + st * STAGE;
        const uint32_t sA_l = sA_h + 16384;
        const uint32_t sB_h = sA_h + NSA * 16384;

#pragma unroll
        for (int k16 = 0; k16 < 4; k16++) {
            uint32_t ah[2][4], al_[2][4];
#pragma unroll
            for (int mi = 0; mi < 2; mi++) {
                int rA = wm + (mi << 4) + (lane & 15);
                int cA = (k16 << 1) + (lane >> 4);
                uint32_t off = rA * 128 + ((cA ^ (rA & 7)) << 4);
                ldsm4(ah[mi], sA_h + off);
                if (NSA == 2) ldsm4(al_[mi], sA_l + off);
            }
            uint32_t bh[4][4];
#pragma unroll
            for (int ng = 0; ng < 4; ng++) {
                int rB = wn + (ng << 4) + (lane & 7) + ((lane & 16) >> 1);
                int cB = (k16 << 1) + ((lane >> 3) & 1);
                uint32_t off = rB * 128 + ((cB ^ (rB & 7)) << 4);
                ldsm4(bh[ng], sB_h + off);
            }
#pragma unroll
            for (int mi = 0; mi < 2; mi++)
#pragma unroll
                for (int ng = 0; ng < 4; ng++)
#pragma unroll
                    for (int s2 = 0; s2 < 2; s2++) {
                        float* cc = acc[mi][ng * 2 + s2];
                        mma16816(cc, ah[mi], &bh[ng][s2 * 2]);
                        if (NSA == 2) mma16816(cc, al_[mi], &bh[ng][s2 * 2]);
                    }
        }
        __syncthreads();
        st = st + 1 == 3 ? 0 : st + 1;
    }
#undef LOAD_STAGE

    // ---------------- epilogue ----------------
    const int rq = lane >> 2;
    const int cq = (lane & 3) << 1;

    if (PHASE == 1) {
        float rs[2][2] = {{0.f, 0.f}, {0.f, 0.f}};
        float bv[2][2] = {{-1e30f, -1e30f}, {-1e30f, -1e30f}};
        int   bi[2][2] = {{0, 0}, {0, 0}};
#pragma unroll
        for (int mi = 0; mi < 2; mi++)
#pragma unroll
            for (int ni = 0; ni < 8; ni++) {
                float* cc = acc[mi][ni];
                int colb = n0 + wn + ni * 8 + cq;
#pragma unroll
                for (int h = 0; h < 2; h++) {
                    float v0 = cc[h * 2], v1 = cc[h * 2 + 1];
                    float e0 = __expf(v0), e1 = __expf(v1);
                    rs[mi][h] += e0 + e1;
                    if (v0 > bv[mi][h]) { bv[mi][h] = v0; bi[mi][h] = colb; }
                    if (v1 > bv[mi][h]) { bv[mi][h] = v1; bi[mi][h] = colb + 1; }
                    __half h0, l0, h1, l1;
                    hsplit(e0, h0, l0); hsplit(e1, h1, l1);
                    int row = m0 + wm + mi * 16 + rq + h * 8;
                    size_t o = (size_t)row * Ndim + colb;
                    *(uint32_t*)&g_Wh[o] = pkh(h0, h1);
                    *(uint32_t*)&g_Wl[o] = pkh(l0, l1);
                }
            }
#pragma unroll
        for (int mi = 0; mi < 2; mi++)
#pragma unroll
            for (int h = 0; h < 2; h++) {
#pragma unroll
                for (int o = 1; o <= 2; o <<= 1) {
                    rs[mi][h] += __shfl_xor_sync(0xffffffffu, rs[mi][h], o);
                    float ov = __shfl_xor_sync(0xffffffffu, bv[mi][h], o);
                    int   oi = __shfl_xor_sync(0xffffffffu, bi[mi][h], o);
                    if (ov > bv[mi][h]) { bv[mi][h] = ov; bi[mi][h] = oi; }
                }
                if ((lane & 3) == 0) {
                    int row = m0 + wm + mi * 16 + rq + h * 8;
                    atomicAdd(&g_rowsum[row], rs[mi][h]);
                    unsigned long long key =
                        ((unsigned long long)keyenc(bv[mi][h]) << 32) | (unsigned int)bi[mi][h];
                    atomicMax(&g_rowmax[row], key);
                }
            }
    } else {
#pragma unroll
        for (int mi = 0; mi < 2; mi++)
#pragma unroll
            for (int h = 0; h < 2; h++) {
                int row = m0 + wm + mi * 16 + rq + h * 8;
                float inv = 1.0f / g_rowsum[row];
#pragma unroll
                for (int ni = 0; ni < 8; ni++) {
                    float* cc = acc[mi][ni];
                    int col = n0 + wn + ni * 8 + cq;
                    float2 v = make_float2(cc[h * 2] * inv, cc[h * 2 + 1] * inv);
                    *(float2*)&out[(size_t)row * Hdim + col] = v;
                }
            }
    }
}

// ---------------- argmax correction: exact fp32 recheck for near-ties ----------------
__global__ void k_argmax_fix(const float* __restrict__ z) {
    const int wid = threadIdx.x >> 5, lane = threadIdx.x & 31;
    const int row = blockIdx.x * 8 + wid;
    __shared__ int s_cnt[8];
    __shared__ int s_cand[8][8];

    const __half* wh = g_Wh + (size_t)row * Ndim;
    const __half* wl = g_Wl + (size_t)row * Ndim;

    float a1 = -1e30f, a2 = -1e30f;
    for (int t = 0; t < Ndim / 32; t++) {
        int j = t * 32 + lane;
        float wv = __half2float(wh[j]) + __half2float(wl[j]);
        if (wv > a1) { a2 = a1; a1 = wv; }
        else if (wv > a2) { a2 = wv; }
    }
#pragma unroll
    for (int o = 16; o; o >>= 1) {
        float b1 = __shfl_down_sync(0xffffffffu, a1, o);
        float b2 = __shfl_down_sync(0xffffffffu, a2, o);
        if (b1 > a1) { a2 = fmaxf(a1, b2); a1 = b1; }
        else if (b1 > a2) { a2 = b1; }
    }
    a1 = __shfl_sync(0xffffffffu, a1, 0);
    a2 = __shfl_sync(0xffffffffu, a2, 0);

    float thr = a1 * (1.0f - 4e-4f);
    if (a2 < thr) return;   // unambiguous: keep gemm1 argmax

    if (lane == 0) s_cnt[wid] = 0;
    __syncwarp();
    for (int t = 0; t < Ndim / 32; t++) {
        int j = t * 32 + lane;
        float wv = __half2float(wh[j]) + __half2float(wl[j]);
        if (wv >= thr) {
            int p = atomicAdd(&s_cnt[wid], 1);
            if (p < 8) s_cand[wid][p] = j;
        }
    }
    __syncwarp();
    int cnt = min(s_cnt[wid], 8);

    float zin = g_zinv[row];
    const float* zr = z + (size_t)row * Hdim;
    float best = -1e30f;
    int bi = -1;
    for (int c = 0; c < cnt; c++) {
        int j = s_cand[wid][c];
        const float* mr = g_mn + (size_t)j * Hdim;
        float s = 0.0f;
        for (int t = 0; t < 16; t++) {
            int h = t * 32 + lane;
            s += zr[h] * zin * mr[h];
        }
#pragma unroll
        for (int o = 16; o; o >>= 1) s += __shfl_down_sync(0xffffffffu, s, o);
        s = __shfl_sync(0xffffffffu, s, 0);
        if (s > best) { best = s; bi = j; }
    }
    if (lane == 0)
        g_rowmax[row] = ((unsigned long long)keyenc(best) << 32) | (unsigned int)bi;
}

// ---------------- column max over argmax rows ----------------
__global__ void k_colmax() {
    int b = blockIdx.x * blockDim.x + threadIdx.x;
    if (b >= Bdim) return;
    unsigned long long key = g_rowmax[b];
    atomicMax(&g_colmax[key & 0xFFFFFFFFull], (unsigned int)(key >> 32));
}

// ---------------- scatter update ----------------
__global__ void k_scatter(const float* __restrict__ z) {
    int row = blockIdx.x * 8 + (threadIdx.x >> 5);
    int lane = threadIdx.x & 31;
    if (row >= Bdim) return;
    unsigned long long key = g_rowmax[row];
    int idx = (int)(key & 0xFFFFFFFFull);
    float val = keydec((unsigned int)(key >> 32));
    float cm = keydec(g_colmax[idx]);
    float p = __expf(val - cm);
    if (lane == 0) atomicAdd(&g_denom[idx], p);
    const float* zr = z + (size_t)row * Hdim;
    float* up = g_update + (size_t)idx * Hdim;
#pragma unroll
    for (int h = 0; h < Hdim; h += 32)
        atomicAdd(&up[h + lane], p * zr[h + lane]);
}

// ---------------- finalize new_memory ----------------
__global__ void k_finalize(const float* __restrict__ mem, float* __restrict__ out) {
    int i = blockIdx.x;
    __shared__ float red[256];
    float d = g_denom[i];
    const float* mr = mem + (size_t)i * Hdim;
    float* o = out + (size_t)Bdim * Hdim + (size_t)i * Hdim;
    if (d > 0.0f) {
        float invd = 1.0f / d;
        float v0 = mr[threadIdx.x]       + g_update[(size_t)i * Hdim + threadIdx.x] * invd;
        float v1 = mr[threadIdx.x + 256] + g_update[(size_t)i * Hdim + threadIdx.x + 256] * invd;
        red[threadIdx.x] = v0 * v0 + v1 * v1;
        __syncthreads();
        for (int s = 128; s > 0; s >>= 1) {
            if (threadIdx.x < s) red[threadIdx.x] += red[threadIdx.x + s];
            __syncthreads();
        }
        float inv = 1.0f / fmaxf(sqrtf(red[0]), 1e-12f);
        o[threadIdx.x]       = v0 * inv;
        o[threadIdx.x + 256] = v1 * inv;
    } else {
        o[threadIdx.x]       = mr[threadIdx.x];
        o[threadIdx.x + 256] = mr[threadIdx.x + 256];
    }
}

// ---------------- launch ----------------
extern "C" void kernel_launch(void* const* d_in, const int* in_sizes, int n_in,
                              void* d_out, int out_size) {
    (void)in_sizes; (void)n_in; (void)out_size;
    const float* z   = (const float*)d_in[0];
    const float* mem = (const float*)d_in[1];
    float* out = (float*)d_out;

    const int DS1 = 3 * 2 * 16384;   // 96KB
    const int DS2 = 3 * 3 * 16384;   // 144KB
    cudaFuncSetAttribute(k_gemm_mma<Hdim, 1>, cudaFuncAttributeMaxDynamicSharedMemorySize, DS1);
    cudaFuncSetAttribute(k_gemm_mma<Ndim, 2>, cudaFuncAttributeMaxDynamicSharedMemorySize, DS2);

    k_zero<<<1024, 256>>>();
    k_norm_mem<<<Ndim, 256>>>(mem);
    k_zsplit<<<Bdim, 256>>>(z);
    k_memT<<<dim3(Hdim / 32, Ndim / 32), dim3(32, 8)>>>(mem);
    k_gemm_mma<Hdim, 1><<<dim3(Ndim / 128, Bdim / 128), 256, DS1>>>(nullptr);
    k_argmax_fix<<<Bdim / 8, 256>>>(z);
    k_gemm_mma<Ndim, 2><<<dim3(Hdim / 128, Bdim / 128), 256, DS2>>>(out);
    k_colmax<<<Bdim / 256, 256>>>();
    k_scatter<<<Bdim / 8, 256>>>(z);
    k_finalize<<<Ndim, 256>>>(mem, out);
}

// round 5
// speedup vs baseline: 5.3076x; 1.3548x over previous
#include <cuda_runtime.h>
#include <cuda_fp16.h>
#include <math.h>
#include <stdint.h>

#define Bdim 32768
#define Ndim 2048
#define Hdim 512

// ---------------- scratch (device globals; no allocation allowed) ----------------
__device__ __align__(16) float g_mn[Ndim * Hdim];            // normalized memory fp32
__device__ float g_zinv[Bdim];
__device__ __align__(16) __half g_zh[(size_t)Bdim * Hdim];   // normalized z fp16
__device__ __align__(16) __half g_mh[Ndim * Hdim];           // normalized mem fp16
__device__ __align__(16) __half g_mth[Hdim * Ndim];          // mem^T fp16 (raw mem)
__device__ __align__(16) __half g_Wh[(size_t)Bdim * Ndim];   // exp(sim) fp16
__device__ float g_rowsum[Bdim];
__device__ unsigned long long g_rowmax[Bdim];                // (keyenc(val)<<32)|idx
__device__ unsigned int g_colmax[Ndim];
__device__ float g_denom[Ndim];
__device__ float g_update[Ndim * Hdim];

// ---------------- helpers ----------------
__device__ __forceinline__ unsigned int keyenc(float f) {
    unsigned int b = __float_as_uint(f);
    return (b & 0x80000000u) ? ~b : (b | 0x80000000u);
}
__device__ __forceinline__ float keydec(unsigned int v) {
    unsigned int b = (v & 0x80000000u) ? (v ^ 0x80000000u) : ~v;
    return __uint_as_float(b);
}
__device__ __forceinline__ unsigned int pkh(__half a, __half b) {
    return ((unsigned int)__half_as_ushort(b) << 16) | (unsigned int)__half_as_ushort(a);
}
__device__ __forceinline__ uint32_t smem_u32(const void* p) {
    uint32_t a;
    asm("{ .reg .u64 t; cvta.to.shared.u64 t, %1; cvt.u32.u64 %0, t; }" : "=r"(a) : "l"(p));
    return a;
}
__device__ __forceinline__ int swz(int off) { return off ^ ((off >> 3) & 0x70); }

__device__ __forceinline__ void cp16(uint32_t d, const void* s) {
    asm volatile("cp.async.cg.shared.global [%0], [%1], 16;" :: "r"(d), "l"(s));
}
#define CP_COMMIT() asm volatile("cp.async.commit_group;" ::: "memory")
#define CP_WAIT(n)  asm volatile("cp.async.wait_group %0;" :: "n"(n) : "memory")

__device__ __forceinline__ void ldsm4(uint32_t* r, uint32_t a) {
    asm volatile("ldmatrix.sync.aligned.m8n8.x4.shared.b16 {%0,%1,%2,%3}, [%4];"
        : "=r"(r[0]), "=r"(r[1]), "=r"(r[2]), "=r"(r[3]) : "r"(a));
}
__device__ __forceinline__ void mma16816(float* c, const uint32_t* a, const uint32_t* b) {
    asm volatile(
        "mma.sync.aligned.m16n8k16.row.col.f32.f16.f16.f32 "
        "{%0,%1,%2,%3},{%4,%5,%6,%7},{%8,%9},{%0,%1,%2,%3};"
        : "+f"(c[0]), "+f"(c[1]), "+f"(c[2]), "+f"(c[3])
        : "r"(a[0]), "r"(a[1]), "r"(a[2]), "r"(a[3]), "r"(b[0]), "r"(b[1]));
}

// ---------------- K0: zero scratch ----------------
__global__ void k_zero() {
    int i = blockIdx.x * blockDim.x + threadIdx.x;
    int stride = gridDim.x * blockDim.x;
    for (int j = i; j < Ndim * Hdim; j += stride) g_update[j] = 0.0f;
    for (int j = i; j < Bdim; j += stride) { g_rowsum[j] = 0.0f; g_rowmax[j] = 0ull; }
    for (int j = i; j < Ndim; j += stride) { g_colmax[j] = 0u; g_denom[j] = 0.0f; }
}

// ---------------- normalize memory -> g_mn fp32 + fp16 ----------------
__global__ void k_norm_mem(const float* __restrict__ mem) {
    int i = blockIdx.x;
    __shared__ float red[256];
    const float* r = mem + (size_t)i * Hdim;
    float v0 = r[threadIdx.x];
    float v1 = r[threadIdx.x + 256];
    red[threadIdx.x] = v0 * v0 + v1 * v1;
    __syncthreads();
    for (int s = 128; s > 0; s >>= 1) {
        if (threadIdx.x < s) red[threadIdx.x] += red[threadIdx.x + s];
        __syncthreads();
    }
    float inv = 1.0f / fmaxf(sqrtf(red[0]), 1e-12f);
    float n0 = v0 * inv, n1 = v1 * inv;
    size_t b = (size_t)i * Hdim + threadIdx.x;
    g_mn[b] = n0; g_mn[b + 256] = n1;
    g_mh[b] = __float2half_rn(n0);
    g_mh[b + 256] = __float2half_rn(n1);
}

// ---------------- normalize z -> zinv + fp16 ----------------
__global__ void k_zsplit(const float* __restrict__ z) {
    int b = blockIdx.x;
    __shared__ float red[256];
    const float* r = z + (size_t)b * Hdim;
    float v0 = r[threadIdx.x];
    float v1 = r[threadIdx.x + 256];
    red[threadIdx.x] = v0 * v0 + v1 * v1;
    __syncthreads();
    for (int s = 128; s > 0; s >>= 1) {
        if (threadIdx.x < s) red[threadIdx.x] += red[threadIdx.x + s];
        __syncthreads();
    }
    float inv = 1.0f / fmaxf(sqrtf(red[0]), 1e-12f);
    if (threadIdx.x == 0) g_zinv[b] = inv;
    size_t o = (size_t)b * Hdim + threadIdx.x;
    g_zh[o] = __float2half_rn(v0 * inv);
    g_zh[o + 256] = __float2half_rn(v1 * inv);
}

// ---------------- transpose raw mem -> memT fp16 ----------------
__global__ void k_memT(const float* __restrict__ mem) {
    __shared__ float t[32][33];
    int h0 = blockIdx.x * 32, n0 = blockIdx.y * 32;
    int tx = threadIdx.x, ty = threadIdx.y;
#pragma unroll
    for (int i = 0; i < 4; i++)
        t[ty + 8 * i][tx] = mem[(size_t)(n0 + ty + 8 * i) * Hdim + h0 + tx];
    __syncthreads();
#pragma unroll
    for (int i = 0; i < 4; i++) {
        int h = h0 + ty + 8 * i, n = n0 + tx;
        g_mth[(size_t)h * Ndim + n] = __float2half_rn(t[tx][ty + 8 * i]);
    }
}

// ---------------- mma.sync GEMM (128x128 block, BK=64, 3-stage cp.async) ----------------
// PHASE 1: sim = zh @ mh^T -> exp, Wh, rowsum, rowmax
// PHASE 2: zhat = Wh @ mth^T / rowsum -> out
template <int KTOT, int PHASE>
__global__ __launch_bounds__(256, 1)
void k_gemm_mma(float* __restrict__ out) {
    constexpr int NC = KTOT / 64;
    constexpr int STAGE = 2 * 16384;
    extern __shared__ __align__(128) char smraw[];
    const uint32_t smb = smem_u32(smraw);

    const int tid = threadIdx.x;
    const int lane = tid & 31;
    const int w = tid >> 5;
    const int wm = (w & 3) << 5;              // warp row base (0..96)
    const int wn = (w >> 2) << 6;             // warp col base (0/64)
    const int m0 = blockIdx.y << 7;
    const int n0 = blockIdx.x << 7;

    const __half *Ah, *Bh;
    if (PHASE == 1) { Ah = g_zh; Bh = g_mh;  }
    else            { Ah = g_Wh; Bh = g_mth; }

    // cp.async granule mapping: 4 per operand per thread
    int grow[4], gcol[4], gswo[4];
#pragma unroll
    for (int q = 0; q < 4; q++) {
        int id = tid + (q << 8);
        grow[q] = id >> 3;
        gcol[q] = (id & 7) << 3;
        gswo[q] = swz(grow[q] * 128 + ((id & 7) << 4));
    }

    float acc[2][8][4];
#pragma unroll
    for (int i = 0; i < 2; i++)
#pragma unroll
        for (int j = 0; j < 8; j++)
#pragma unroll
            for (int q = 0; q < 4; q++) acc[i][j][q] = 0.0f;

#define LOAD_STAGE(c, s) do {                                                        \
    uint32_t sb_ = smb + (s) * STAGE;                                                \
    size_t k0_ = (size_t)((c) << 6);                                                 \
    _Pragma("unroll")                                                                \
    for (int q = 0; q < 4; q++) {                                                    \
        size_t ao_ = (size_t)(m0 + grow[q]) * KTOT + k0_ + gcol[q];                  \
        size_t bo_ = (size_t)(n0 + grow[q]) * KTOT + k0_ + gcol[q];                  \
        cp16(sb_ + gswo[q],         Ah + ao_);                                       \
        cp16(sb_ + 16384 + gswo[q], Bh + bo_);                                       \
    }                                                                                \
    CP_COMMIT();                                                                     \
} while (0)

    LOAD_STAGE(0, 0);
    if (NC > 1) LOAD_STAGE(1, 1); else CP_COMMIT();

    int st = 0;
    for (int c = 0; c < NC; c++) {
        int pf = c + 2;
        int pst = st + 2; if (pst >= 3) pst -= 3;
        if (pf < NC) { LOAD_STAGE(pf, pst); } else { CP_COMMIT(); }
        CP_WAIT(2);
        __syncthreads();

        const uint32_t sA_h = smb + st * STAGE;
        const uint32_t sB_h = sA_h + 16384;

#pragma unroll
        for (int k16 = 0; k16 < 4; k16++) {
            uint32_t ah[2][4];
#pragma unroll
            for (int mi = 0; mi < 2; mi++) {
                int rA = wm + (mi << 4) + (lane & 15);
                int cA = (k16 << 1) + (lane >> 4);
                uint32_t off = rA * 128 + ((cA ^ (rA & 7)) << 4);
                ldsm4(ah[mi], sA_h + off);
            }
            uint32_t bh[4][4];
#pragma unroll
            for (int ng = 0; ng < 4; ng++) {
                int rB = wn + (ng << 4) + (lane & 7) + ((lane & 16) >> 1);
                int cB = (k16 << 1) + ((lane >> 3) & 1);
                uint32_t off = rB * 128 + ((cB ^ (rB & 7)) << 4);
                ldsm4(bh[ng], sB_h + off);
            }
#pragma unroll
            for (int mi = 0; mi < 2; mi++)
#pragma unroll
                for (int ng = 0; ng < 4; ng++)
#pragma unroll
                    for (int s2 = 0; s2 < 2; s2++)
                        mma16816(acc[mi][ng * 2 + s2], ah[mi], &bh[ng][s2 * 2]);
        }
        __syncthreads();
        st = st + 1 == 3 ? 0 : st + 1;
    }
#undef LOAD_STAGE

    // ---------------- epilogue ----------------
    const int rq = lane >> 2;
    const int cq = (lane & 3) << 1;

    if (PHASE == 1) {
        float rs[2][2] = {{0.f, 0.f}, {0.f, 0.f}};
        float bv[2][2] = {{-1e30f, -1e30f}, {-1e30f, -1e30f}};
        int   bi[2][2] = {{0, 0}, {0, 0}};
#pragma unroll
        for (int mi = 0; mi < 2; mi++)
#pragma unroll
            for (int ni = 0; ni < 8; ni++) {
                float* cc = acc[mi][ni];
                int colb = n0 + wn + ni * 8 + cq;
#pragma unroll
                for (int h = 0; h < 2; h++) {
                    float v0 = cc[h * 2], v1 = cc[h * 2 + 1];
                    float e0 = __expf(v0), e1 = __expf(v1);
                    rs[mi][h] += e0 + e1;
                    if (v0 > bv[mi][h]) { bv[mi][h] = v0; bi[mi][h] = colb; }
                    if (v1 > bv[mi][h]) { bv[mi][h] = v1; bi[mi][h] = colb + 1; }
                    int row = m0 + wm + mi * 16 + rq + h * 8;
                    size_t o = (size_t)row * Ndim + colb;
                    *(uint32_t*)&g_Wh[o] = pkh(__float2half_rn(e0), __float2half_rn(e1));
                }
            }
#pragma unroll
        for (int mi = 0; mi < 2; mi++)
#pragma unroll
            for (int h = 0; h < 2; h++) {
#pragma unroll
                for (int o = 1; o <= 2; o <<= 1) {
                    rs[mi][h] += __shfl_xor_sync(0xffffffffu, rs[mi][h], o);
                    float ov = __shfl_xor_sync(0xffffffffu, bv[mi][h], o);
                    int   oi = __shfl_xor_sync(0xffffffffu, bi[mi][h], o);
                    if (ov > bv[mi][h]) { bv[mi][h] = ov; bi[mi][h] = oi; }
                }
                if ((lane & 3) == 0) {
                    int row = m0 + wm + mi * 16 + rq + h * 8;
                    atomicAdd(&g_rowsum[row], rs[mi][h]);
                    unsigned long long key =
                        ((unsigned long long)keyenc(bv[mi][h]) << 32) | (unsigned int)bi[mi][h];
                    atomicMax(&g_rowmax[row], key);
                }
            }
    } else {
#pragma unroll
        for (int mi = 0; mi < 2; mi++)
#pragma unroll
            for (int h = 0; h < 2; h++) {
                int row = m0 + wm + mi * 16 + rq + h * 8;
                float inv = 1.0f / g_rowsum[row];
#pragma unroll
                for (int ni = 0; ni < 8; ni++) {
                    float* cc = acc[mi][ni];
                    int col = n0 + wn + ni * 8 + cq;
                    float2 v = make_float2(cc[h * 2] * inv, cc[h * 2 + 1] * inv);
                    *(float2*)&out[(size_t)row * Hdim + col] = v;
                }
            }
    }
}

// ---------------- argmax correction: exact fp32 recheck for near-ties ----------------
__global__ void k_argmax_fix(const float* __restrict__ z) {
    const int wid = threadIdx.x >> 5, lane = threadIdx.x & 31;
    const int row = blockIdx.x * 8 + wid;
    __shared__ int s_cnt[8];
    __shared__ int s_cand[8][16];

    const __half* wh = g_Wh + (size_t)row * Ndim;

    float a1 = -1e30f, a2 = -1e30f;
    for (int t = 0; t < Ndim / 32; t++) {
        int j = t * 32 + lane;
        float wv = __half2float(wh[j]);
        if (wv > a1) { a2 = a1; a1 = wv; }
        else if (wv > a2) { a2 = wv; }
    }
#pragma unroll
    for (int o = 16; o; o >>= 1) {
        float b1 = __shfl_down_sync(0xffffffffu, a1, o);
        float b2 = __shfl_down_sync(0xffffffffu, a2, o);
        if (b1 > a1) { a2 = fmaxf(a1, b2); a1 = b1; }
        else if (b1 > a2) { a2 = b1; }
    }
    a1 = __shfl_sync(0xffffffffu, a1, 0);
    a2 = __shfl_sync(0xffffffffu, a2, 0);

    float thr = a1 * (1.0f - 1e-3f);
    if (a2 < thr) return;   // unambiguous: keep gemm1 argmax

    if (lane == 0) s_cnt[wid] = 0;
    __syncwarp();
    for (int t = 0; t < Ndim / 32; t++) {
        int j = t * 32 + lane;
        float wv = __half2float(wh[j]);
        if (wv >= thr) {
            int p = atomicAdd(&s_cnt[wid], 1);
            if (p < 16) s_cand[wid][p] = j;
        }
    }
    __syncwarp();
    int cnt = min(s_cnt[wid], 16);

    float zin = g_zinv[row];
    const float* zr = z + (size_t)row * Hdim;
    float best = -1e30f;
    int bi = -1;
    for (int c = 0; c < cnt; c++) {
        int j = s_cand[wid][c];
        const float* mr = g_mn + (size_t)j * Hdim;
        float s = 0.0f;
        for (int t = 0; t < 16; t++) {
            int h = t * 32 + lane;
            s += zr[h] * zin * mr[h];
        }
#pragma unroll
        for (int o = 16; o; o >>= 1) s += __shfl_down_sync(0xffffffffu, s, o);
        s = __shfl_sync(0xffffffffu, s, 0);
        if (s > best) { best = s; bi = j; }
    }
    if (lane == 0)
        g_rowmax[row] = ((unsigned long long)keyenc(best) << 32) | (unsigned int)bi;
}

// ---------------- column max over argmax rows ----------------
__global__ void k_colmax() {
    int b = blockIdx.x * blockDim.x + threadIdx.x;
    if (b >= Bdim) return;
    unsigned long long key = g_rowmax[b];
    atomicMax(&g_colmax[key & 0xFFFFFFFFull], (unsigned int)(key >> 32));
}

// ---------------- scatter update ----------------
__global__ void k_scatter(const float* __restrict__ z) {
    int row = blockIdx.x * 8 + (threadIdx.x >> 5);
    int lane = threadIdx.x & 31;
    if (row >= Bdim) return;
    unsigned long long key = g_rowmax[row];
    int idx = (int)(key & 0xFFFFFFFFull);
    float val = keydec((unsigned int)(key >> 32));
    float cm = keydec(g_colmax[idx]);
    float p = __expf(val - cm);
    if (lane == 0) atomicAdd(&g_denom[idx], p);
    const float* zr = z + (size_t)row * Hdim;
    float* up = g_update + (size_t)idx * Hdim;
#pragma unroll
    for (int h = 0; h < Hdim; h += 32)
        atomicAdd(&up[h + lane], p * zr[h + lane]);
}

// ---------------- finalize new_memory ----------------
__global__ void k_finalize(const float* __restrict__ mem, float* __restrict__ out) {
    int i = blockIdx.x;
    __shared__ float red[256];
    float d = g_denom[i];
    const float* mr = mem + (size_t)i * Hdim;
    float* o = out + (size_t)Bdim * Hdim + (size_t)i * Hdim;
    if (d > 0.0f) {
        float invd = 1.0f / d;
        float v0 = mr[threadIdx.x]       + g_update[(size_t)i * Hdim + threadIdx.x] * invd;
        float v1 = mr[threadIdx.x + 256] + g_update[(size_t)i * Hdim + threadIdx.x + 256] * invd;
        red[threadIdx.x] = v0 * v0 + v1 * v1;
        __syncthreads();
        for (int s = 128; s > 0; s >>= 1) {
            if (threadIdx.x < s) red[threadIdx.x] += red[threadIdx.x + s];
            __syncthreads();
        }
        float inv = 1.0f / fmaxf(sqrtf(red[0]), 1e-12f);
        o[threadIdx.x]       = v0 * inv;
        o[threadIdx.x + 256] = v1 * inv;
    } else {
        o[threadIdx.x]       = mr[threadIdx.x];
        o[threadIdx.x + 256] = mr[threadIdx.x + 256];
    }
}

// ---------------- launch ----------------
extern "C" void kernel_launch(void* const* d_in, const int* in_sizes, int n_in,
                              void* d_out, int out_size) {
    (void)in_sizes; (void)n_in; (void)out_size;
    const float* z   = (const float*)d_in[0];
    const float* mem = (const float*)d_in[1];
    float* out = (float*)d_out;

    const int DS = 3 * 2 * 16384;   // 96KB
    cudaFuncSetAttribute(k_gemm_mma<Hdim, 1>, cudaFuncAttributeMaxDynamicSharedMemorySize, DS);
    cudaFuncSetAttribute(k_gemm_mma<Ndim, 2>, cudaFuncAttributeMaxDynamicSharedMemorySize, DS);

    k_zero<<<1024, 256>>>();
    k_norm_mem<<<Ndim, 256>>>(mem);
    k_zsplit<<<Bdim, 256>>>(z);
    k_memT<<<dim3(Hdim / 32, Ndim / 32), dim3(32, 8)>>>(mem);
    k_gemm_mma<Hdim, 1><<<dim3(Ndim / 128, Bdim / 128), 256, DS>>>(nullptr);
    k_argmax_fix<<<Bdim / 8, 256>>>(z);
    k_gemm_mma<Ndim, 2><<<dim3(Hdim / 128, Bdim / 128), 256, DS>>>(out);
    k_colmax<<<Bdim / 256, 256>>>();
    k_scatter<<<Bdim / 8, 256>>>(z);
    k_finalize<<<Ndim, 256>>>(mem, out);
}

// round 6
// speedup vs baseline: 5.6003x; 1.0551x over previous
#include <cuda_runtime.h>
#include <cuda_fp16.h>
#include <math.h>
#include <stdint.h>

#define Bdim 32768
#define Ndim 2048
#define Hdim 512

// ---------------- scratch (device globals; no allocation allowed) ----------------
__device__ __align__(16) float g_mn[Ndim * Hdim];            // normalized memory fp32
__device__ float g_zinv[Bdim];
__device__ __align__(16) __half g_zh[(size_t)Bdim * Hdim];   // normalized z fp16
__device__ __align__(16) __half g_mh[Ndim * Hdim];           // normalized mem fp16
__device__ __align__(16) __half g_mth[Hdim * Ndim];          // mem^T fp16 (raw mem)
__device__ __align__(16) __half g_Wh[(size_t)Bdim * Ndim];   // exp(sim) fp16
__device__ float g_rowsum[Bdim];
__device__ unsigned long long g_rowmax[Bdim];                // (keyenc(val)<<32)|idx
__device__ unsigned int g_colmax[Ndim];
__device__ unsigned int g_cnt[Ndim];
__device__ unsigned int g_off[Ndim];
__device__ unsigned int g_cur[Ndim];
__device__ unsigned int g_rowlist[Bdim];

// ---------------- helpers ----------------
__device__ __forceinline__ unsigned int keyenc(float f) {
    unsigned int b = __float_as_uint(f);
    return (b & 0x80000000u) ? ~b : (b | 0x80000000u);
}
__device__ __forceinline__ float keydec(unsigned int v) {
    unsigned int b = (v & 0x80000000u) ? (v ^ 0x80000000u) : ~v;
    return __uint_as_float(b);
}
__device__ __forceinline__ unsigned int pkh(__half a, __half b) {
    return ((unsigned int)__half_as_ushort(b) << 16) | (unsigned int)__half_as_ushort(a);
}
__device__ __forceinline__ uint32_t smem_u32(const void* p) {
    uint32_t a;
    asm("{ .reg .u64 t; cvta.to.shared.u64 t, %1; cvt.u32.u64 %0, t; }" : "=r"(a) : "l"(p));
    return a;
}

__device__ __forceinline__ void cp16(uint32_t d, const void* s) {
    asm volatile("cp.async.cg.shared.global [%0], [%1], 16;" :: "r"(d), "l"(s));
}
#define CP_COMMIT() asm volatile("cp.async.commit_group;" ::: "memory")
#define CP_WAIT(n)  asm volatile("cp.async.wait_group %0;" :: "n"(n) : "memory")

__device__ __forceinline__ void ldsm4(uint32_t* r, uint32_t a) {
    asm volatile("ldmatrix.sync.aligned.m8n8.x4.shared.b16 {%0,%1,%2,%3}, [%4];"
        : "=r"(r[0]), "=r"(r[1]), "=r"(r[2]), "=r"(r[3]) : "r"(a));
}
__device__ __forceinline__ void mma16816(float* c, const uint32_t* a, const uint32_t* b) {
    asm volatile(
        "mma.sync.aligned.m16n8k16.row.col.f32.f16.f16.f32 "
        "{%0,%1,%2,%3},{%4,%5,%6,%7},{%8,%9},{%0,%1,%2,%3};"
        : "+f"(c[0]), "+f"(c[1]), "+f"(c[2]), "+f"(c[3])
        : "r"(a[0]), "r"(a[1]), "r"(a[2]), "r"(a[3]), "r"(b[0]), "r"(b[1]));
}

// ---------------- K0: zero scratch ----------------
__global__ void k_zero() {
    int i = blockIdx.x * blockDim.x + threadIdx.x;
    int stride = gridDim.x * blockDim.x;
    for (int j = i; j < Bdim; j += stride) { g_rowsum[j] = 0.0f; g_rowmax[j] = 0ull; }
    for (int j = i; j < Ndim; j += stride) { g_colmax[j] = 0u; g_cnt[j] = 0u; }
}

// ---------------- normalize memory -> g_mn fp32 + fp16 ----------------
__global__ void k_norm_mem(const float* __restrict__ mem) {
    int i = blockIdx.x;
    __shared__ float red[256];
    const float* r = mem + (size_t)i * Hdim;
    float v0 = r[threadIdx.x];
    float v1 = r[threadIdx.x + 256];
    red[threadIdx.x] = v0 * v0 + v1 * v1;
    __syncthreads();
    for (int s = 128; s > 0; s >>= 1) {
        if (threadIdx.x < s) red[threadIdx.x] += red[threadIdx.x + s];
        __syncthreads();
    }
    float inv = 1.0f / fmaxf(sqrtf(red[0]), 1e-12f);
    float n0 = v0 * inv, n1 = v1 * inv;
    size_t b = (size_t)i * Hdim + threadIdx.x;
    g_mn[b] = n0; g_mn[b + 256] = n1;
    g_mh[b] = __float2half_rn(n0);
    g_mh[b + 256] = __float2half_rn(n1);
}

// ---------------- normalize z -> zinv + fp16 ----------------
__global__ void k_zsplit(const float* __restrict__ z) {
    int b = blockIdx.x;
    __shared__ float red[256];
    const float* r = z + (size_t)b * Hdim;
    float v0 = r[threadIdx.x];
    float v1 = r[threadIdx.x + 256];
    red[threadIdx.x] = v0 * v0 + v1 * v1;
    __syncthreads();
    for (int s = 128; s > 0; s >>= 1) {
        if (threadIdx.x < s) red[threadIdx.x] += red[threadIdx.x + s];
        __syncthreads();
    }
    float inv = 1.0f / fmaxf(sqrtf(red[0]), 1e-12f);
    if (threadIdx.x == 0) g_zinv[b] = inv;
    size_t o = (size_t)b * Hdim + threadIdx.x;
    g_zh[o] = __float2half_rn(v0 * inv);
    g_zh[o + 256] = __float2half_rn(v1 * inv);
}

// ---------------- transpose raw mem -> memT fp16 ----------------
__global__ void k_memT(const float* __restrict__ mem) {
    __shared__ float t[32][33];
    int h0 = blockIdx.x * 32, n0 = blockIdx.y * 32;
    int tx = threadIdx.x, ty = threadIdx.y;
#pragma unroll
    for (int i = 0; i < 4; i++)
        t[ty + 8 * i][tx] = mem[(size_t)(n0 + ty + 8 * i) * Hdim + h0 + tx];
    __syncthreads();
#pragma unroll
    for (int i = 0; i < 4; i++) {
        int h = h0 + ty + 8 * i, n = n0 + tx;
        g_mth[(size_t)h * Ndim + n] = __float2half_rn(t[tx][ty + 8 * i]);
    }
}

// ---------------- mma.sync GEMM (128x128 block, BK=128, 2-stage cp.async) ----------------
// PHASE 1: sim = zh @ mh^T -> exp, Wh, rowsum, rowmax
// PHASE 2: zhat = Wh @ mth^T / rowsum -> out
template <int KTOT, int PHASE>
__global__ __launch_bounds__(256, 1)
void k_gemm_mma(float* __restrict__ out) {
    constexpr int NC = KTOT / 128;
    constexpr int STAGE = 2 * 32768;          // A(32KB)+B(32KB)
    extern __shared__ __align__(128) char smraw[];
    const uint32_t smb = smem_u32(smraw);

    const int tid = threadIdx.x;
    const int lane = tid & 31;
    const int w = tid >> 5;
    const int wm = (w & 3) << 5;              // warp row base (0..96)
    const int wn = (w >> 2) << 6;             // warp col base (0/64)
    const int m0 = blockIdx.y << 7;
    const int n0 = blockIdx.x << 7;

    const __half *Ah, *Bh;
    if (PHASE == 1) { Ah = g_zh; Bh = g_mh;  }
    else            { Ah = g_Wh; Bh = g_mth; }

    // cp.async granule mapping: 8 per operand per thread (128 rows x 256B)
    int grow[8], gcol[8], gswo[8];
#pragma unroll
    for (int q = 0; q < 8; q++) {
        int id = tid + (q << 8);
        grow[q] = id >> 4;
        gcol[q] = (id & 15) << 3;
        gswo[q] = grow[q] * 256 + (((id & 15) ^ (grow[q] & 7)) << 4);
    }

    float acc[2][8][4];
#pragma unroll
    for (int i = 0; i < 2; i++)
#pragma unroll
        for (int j = 0; j < 8; j++)
#pragma unroll
            for (int q = 0; q < 4; q++) acc[i][j][q] = 0.0f;

#define LOAD_STAGE(c, s) do {                                                        \
    uint32_t sb_ = smb + (s) * STAGE;                                                \
    size_t k0_ = (size_t)((c) << 7);                                                 \
    _Pragma("unroll")                                                                \
    for (int q = 0; q < 8; q++) {                                                    \
        size_t ao_ = (size_t)(m0 + grow[q]) * KTOT + k0_ + gcol[q];                  \
        size_t bo_ = (size_t)(n0 + grow[q]) * KTOT + k0_ + gcol[q];                  \
        cp16(sb_ + gswo[q],         Ah + ao_);                                       \
        cp16(sb_ + 32768 + gswo[q], Bh + bo_);                                       \
    }                                                                                \
    CP_COMMIT();                                                                     \
} while (0)

    LOAD_STAGE(0, 0);

    for (int c = 0; c < NC; c++) {
        if (c + 1 < NC) { LOAD_STAGE(c + 1, (c + 1) & 1); CP_WAIT(1); }
        else            { CP_WAIT(0); }
        __syncthreads();

        const uint32_t sA = smb + (c & 1) * STAGE;
        const uint32_t sB = sA + 32768;

#pragma unroll
        for (int k16 = 0; k16 < 8; k16++) {
            uint32_t ah[2][4];
#pragma unroll
            for (int mi = 0; mi < 2; mi++) {
                int rA = wm + (mi << 4) + (lane & 15);
                int cA = (k16 << 1) + (lane >> 4);
                uint32_t off = rA * 256 + ((cA ^ (rA & 7)) << 4);
                ldsm4(ah[mi], sA + off);
            }
            uint32_t bh[4][4];
#pragma unroll
            for (int ng = 0; ng < 4; ng++) {
                int rB = wn + (ng << 4) + (lane & 7) + ((lane & 16) >> 1);
                int cB = (k16 << 1) + ((lane >> 3) & 1);
                uint32_t off = rB * 256 + ((cB ^ (rB & 7)) << 4);
                ldsm4(bh[ng], sB + off);
            }
#pragma unroll
            for (int mi = 0; mi < 2; mi++)
#pragma unroll
                for (int ng = 0; ng < 4; ng++)
#pragma unroll
                    for (int s2 = 0; s2 < 2; s2++)
                        mma16816(acc[mi][ng * 2 + s2], ah[mi], &bh[ng][s2 * 2]);
        }
        __syncthreads();
    }
#undef LOAD_STAGE

    // ---------------- epilogue ----------------
    const int rq = lane >> 2;
    const int cq = (lane & 3) << 1;

    if (PHASE == 1) {
        float rs[2][2] = {{0.f, 0.f}, {0.f, 0.f}};
        float bv[2][2] = {{-1e30f, -1e30f}, {-1e30f, -1e30f}};
        int   bi[2][2] = {{0, 0}, {0, 0}};
#pragma unroll
        for (int mi = 0; mi < 2; mi++)
#pragma unroll
            for (int ni = 0; ni < 8; ni++) {
                float* cc = acc[mi][ni];
                int colb = n0 + wn + ni * 8 + cq;
#pragma unroll
                for (int h = 0; h < 2; h++) {
                    float v0 = cc[h * 2], v1 = cc[h * 2 + 1];
                    float e0 = __expf(v0), e1 = __expf(v1);
                    rs[mi][h] += e0 + e1;
                    if (v0 > bv[mi][h]) { bv[mi][h] = v0; bi[mi][h] = colb; }
                    if (v1 > bv[mi][h]) { bv[mi][h] = v1; bi[mi][h] = colb + 1; }
                    int row = m0 + wm + mi * 16 + rq + h * 8;
                    size_t o = (size_t)row * Ndim + colb;
                    *(uint32_t*)&g_Wh[o] = pkh(__float2half_rn(e0), __float2half_rn(e1));
                }
            }
#pragma unroll
        for (int mi = 0; mi < 2; mi++)
#pragma unroll
            for (int h = 0; h < 2; h++) {
#pragma unroll
                for (int o = 1; o <= 2; o <<= 1) {
                    rs[mi][h] += __shfl_xor_sync(0xffffffffu, rs[mi][h], o);
                    float ov = __shfl_xor_sync(0xffffffffu, bv[mi][h], o);
                    int   oi = __shfl_xor_sync(0xffffffffu, bi[mi][h], o);
                    if (ov > bv[mi][h]) { bv[mi][h] = ov; bi[mi][h] = oi; }
                }
                if ((lane & 3) == 0) {
                    int row = m0 + wm + mi * 16 + rq + h * 8;
                    atomicAdd(&g_rowsum[row], rs[mi][h]);
                    unsigned long long key =
                        ((unsigned long long)keyenc(bv[mi][h]) << 32) | (unsigned int)bi[mi][h];
                    atomicMax(&g_rowmax[row], key);
                }
            }
    } else {
#pragma unroll
        for (int mi = 0; mi < 2; mi++)
#pragma unroll
            for (int h = 0; h < 2; h++) {
                int row = m0 + wm + mi * 16 + rq + h * 8;
                float inv = 1.0f / g_rowsum[row];
#pragma unroll
                for (int ni = 0; ni < 8; ni++) {
                    float* cc = acc[mi][ni];
                    int col = n0 + wn + ni * 8 + cq;
                    float2 v = make_float2(cc[h * 2] * inv, cc[h * 2 + 1] * inv);
                    *(float2*)&out[(size_t)row * Hdim + col] = v;
                }
            }
    }
}

// ---------------- argmax correction: exact fp32 recheck for near-ties ----------------
__global__ void k_argmax_fix(const float* __restrict__ z) {
    const int wid = threadIdx.x >> 5, lane = threadIdx.x & 31;
    const int row = blockIdx.x * 8 + wid;
    __shared__ int s_cnt[8];
    __shared__ int s_cand[8][16];

    const __half* wh = g_Wh + (size_t)row * Ndim;

    float a1 = -1e30f, a2 = -1e30f;
    for (int t = 0; t < Ndim / 32; t++) {
        int j = t * 32 + lane;
        float wv = __half2float(wh[j]);
        if (wv > a1) { a2 = a1; a1 = wv; }
        else if (wv > a2) { a2 = wv; }
    }
#pragma unroll
    for (int o = 16; o; o >>= 1) {
        float b1 = __shfl_down_sync(0xffffffffu, a1, o);
        float b2 = __shfl_down_sync(0xffffffffu, a2, o);
        if (b1 > a1) { a2 = fmaxf(a1, b2); a1 = b1; }
        else if (b1 > a2) { a2 = b1; }
    }
    a1 = __shfl_sync(0xffffffffu, a1, 0);
    a2 = __shfl_sync(0xffffffffu, a2, 0);

    float thr = a1 * (1.0f - 1e-3f);
    if (a2 < thr) return;   // unambiguous: keep gemm1 argmax

    if (lane == 0) s_cnt[wid] = 0;
    __syncwarp();
    for (int t = 0; t < Ndim / 32; t++) {
        int j = t * 32 + lane;
        float wv = __half2float(wh[j]);
        if (wv >= thr) {
            int p = atomicAdd(&s_cnt[wid], 1);
            if (p < 16) s_cand[wid][p] = j;
        }
    }
    __syncwarp();
    int cnt = min(s_cnt[wid], 16);

    float zin = g_zinv[row];
    const float* zr = z + (size_t)row * Hdim;
    float best = -1e30f;
    int bi = -1;
    for (int c = 0; c < cnt; c++) {
        int j = s_cand[wid][c];
        const float* mr = g_mn + (size_t)j * Hdim;
        float s = 0.0f;
        for (int t = 0; t < 16; t++) {
            int h = t * 32 + lane;
            s += zr[h] * zin * mr[h];
        }
#pragma unroll
        for (int o = 16; o; o >>= 1) s += __shfl_down_sync(0xffffffffu, s, o);
        s = __shfl_sync(0xffffffffu, s, 0);
        if (s > best) { best = s; bi = j; }
    }
    if (lane == 0)
        g_rowmax[row] = ((unsigned long long)keyenc(best) << 32) | (unsigned int)bi;
}

// ---------------- count rows per slot + column max ----------------
__global__ void k_count() {
    int b = blockIdx.x * blockDim.x + threadIdx.x;
    if (b >= Bdim) return;
    unsigned long long key = g_rowmax[b];
    unsigned int idx = (unsigned int)(key & 0xFFFFFFFFull);
    atomicAdd(&g_cnt[idx], 1u);
    atomicMax(&g_colmax[idx], (unsigned int)(key >> 32));
}

// ---------------- exclusive prefix scan over 2048 counts (one block) ----------------
__global__ void k_prefix() {
    __shared__ unsigned int sa[Ndim], sb[Ndim];
    int t = threadIdx.x;                       // 1024 threads, 2 elems each
    sa[t] = g_cnt[t]; sa[t + 1024] = g_cnt[t + 1024];
    __syncthreads();
    unsigned int* src = sa;
    unsigned int* dst = sb;
    for (int d = 1; d < Ndim; d <<= 1) {
#pragma unroll
        for (int q = 0; q < 2; q++) {
            int i = t + q * 1024;
            dst[i] = src[i] + (i >= d ? src[i - d] : 0u);
        }
        __syncthreads();
        unsigned int* tmp = src; src = dst; dst = tmp;
    }
#pragma unroll
    for (int q = 0; q < 2; q++) {
        int i = t + q * 1024;
        unsigned int excl = src[i] - g_cnt[i];
        g_off[i] = excl;
        g_cur[i] = excl;
    }
}

// ---------------- fill row list ----------------
__global__ void k_fill() {
    int b = blockIdx.x * blockDim.x + threadIdx.x;
    if (b >= Bdim) return;
    unsigned int idx = (unsigned int)(g_rowmax[b] & 0xFFFFFFFFull);
    unsigned int pos = atomicAdd(&g_cur[idx], 1u);
    g_rowlist[pos] = (unsigned int)b;
}

// ---------------- per-slot update + finalize (no atomics) ----------------
__global__ void k_update(const float* __restrict__ z, const float* __restrict__ mem,
                         float* __restrict__ out) {
    int n = blockIdx.x;
    int t = threadIdx.x;
    const float* mr = mem + (size_t)n * Hdim;
    float* o = out + (size_t)Bdim * Hdim + (size_t)n * Hdim;
    int cnt = (int)g_cnt[n];
    if (cnt == 0) {
        o[t] = mr[t];
        o[t + 256] = mr[t + 256];
        return;
    }
    float cm = keydec(g_colmax[n]);
    int off = (int)g_off[n];
    float a0 = 0.0f, a1 = 0.0f, denom = 0.0f;
    for (int r = 0; r < cnt; r++) {
        int row = (int)g_rowlist[off + r];
        unsigned long long key = g_rowmax[row];
        float val = keydec((unsigned int)(key >> 32));
        float p = __expf(val - cm);
        denom += p;
        const float* zr = z + (size_t)row * Hdim;
        a0 += p * zr[t];
        a1 += p * zr[t + 256];
    }
    float invd = 1.0f / denom;
    float v0 = mr[t] + a0 * invd;
    float v1 = mr[t + 256] + a1 * invd;
    __shared__ float red[256];
    red[t] = v0 * v0 + v1 * v1;
    __syncthreads();
    for (int s = 128; s > 0; s >>= 1) {
        if (t < s) red[t] += red[t + s];
        __syncthreads();
    }
    float inv = 1.0f / fmaxf(sqrtf(red[0]), 1e-12f);
    o[t] = v0 * inv;
    o[t + 256] = v1 * inv;
}

// ---------------- launch ----------------
extern "C" void kernel_launch(void* const* d_in, const int* in_sizes, int n_in,
                              void* d_out, int out_size) {
    (void)in_sizes; (void)n_in; (void)out_size;
    const float* z   = (const float*)d_in[0];
    const float* mem = (const float*)d_in[1];
    float* out = (float*)d_out;

    const int DS = 2 * 2 * 32768;   // 128KB
    cudaFuncSetAttribute(k_gemm_mma<Hdim, 1>, cudaFuncAttributeMaxDynamicSharedMemorySize, DS);
    cudaFuncSetAttribute(k_gemm_mma<Ndim, 2>, cudaFuncAttributeMaxDynamicSharedMemorySize, DS);

    k_zero<<<256, 256>>>();
    k_norm_mem<<<Ndim, 256>>>(mem);
    k_zsplit<<<Bdim, 256>>>(z);
    k_memT<<<dim3(Hdim / 32, Ndim / 32), dim3(32, 8)>>>(mem);
    k_gemm_mma<Hdim, 1><<<dim3(Ndim / 128, Bdim / 128), 256, DS>>>(nullptr);
    k_argmax_fix<<<Bdim / 8, 256>>>(z);
    k_count<<<Bdim / 256, 256>>>();
    k_prefix<<<1, 1024>>>();
    k_fill<<<Bdim / 256, 256>>>();
    k_gemm_mma<Ndim, 2><<<dim3(Hdim / 128, Bdim / 128), 256, DS>>>(out);
    k_update<<<Ndim, 256>>>(z, mem, out);
}

// round 7
// speedup vs baseline: 6.9074x; 1.2334x over previous
#include <cuda_runtime.h>
#include <cuda_fp16.h>
#include <math.h>
#include <stdint.h>

#define Bdim 32768
#define Ndim 2048
#define Hdim 512

// ---------------- scratch (device globals; no allocation allowed) ----------------
__device__ __align__(16) float g_mn[Ndim * Hdim];            // normalized memory fp32
__device__ float g_zinv[Bdim];
__device__ __align__(16) __half g_zh[(size_t)Bdim * Hdim];   // normalized z fp16
__device__ __align__(16) __half g_mh[Ndim * Hdim];           // normalized mem fp16
__device__ __align__(16) __half g_mth[Hdim * Ndim];          // mem^T fp16 (raw mem)
__device__ __align__(16) __half g_Wh[(size_t)Bdim * Ndim];   // exp(sim) fp16
__device__ float g_rowsum[Bdim];
__device__ unsigned long long g_rowmax[Bdim];                // (keyenc(val)<<32)|idx
__device__ unsigned int g_colmax[Ndim];
__device__ unsigned int g_cnt[Ndim];
__device__ unsigned int g_off[Ndim];
__device__ unsigned int g_cur[Ndim];
__device__ unsigned int g_rowlist[Bdim];

// ---------------- helpers ----------------
__device__ __forceinline__ unsigned int keyenc(float f) {
    unsigned int b = __float_as_uint(f);
    return (b & 0x80000000u) ? ~b : (b | 0x80000000u);
}
__device__ __forceinline__ float keydec(unsigned int v) {
    unsigned int b = (v & 0x80000000u) ? (v ^ 0x80000000u) : ~v;
    return __uint_as_float(b);
}
__device__ __forceinline__ unsigned int pkh(__half a, __half b) {
    return ((unsigned int)__half_as_ushort(b) << 16) | (unsigned int)__half_as_ushort(a);
}
__device__ __forceinline__ uint32_t smem_u32(const void* p) {
    uint32_t a;
    asm("{ .reg .u64 t; cvta.to.shared.u64 t, %1; cvt.u32.u64 %0, t; }" : "=r"(a) : "l"(p));
    return a;
}

__device__ __forceinline__ void cp16(uint32_t d, const void* s) {
    asm volatile("cp.async.cg.shared.global [%0], [%1], 16;" :: "r"(d), "l"(s));
}
#define CP_COMMIT() asm volatile("cp.async.commit_group;" ::: "memory")
#define CP_WAIT(n)  asm volatile("cp.async.wait_group %0;" :: "n"(n) : "memory")

__device__ __forceinline__ void ldsm4(uint32_t* r, uint32_t a) {
    asm volatile("ldmatrix.sync.aligned.m8n8.x4.shared.b16 {%0,%1,%2,%3}, [%4];"
        : "=r"(r[0]), "=r"(r[1]), "=r"(r[2]), "=r"(r[3]) : "r"(a));
}
__device__ __forceinline__ void mma16816(float* c, const uint32_t* a, const uint32_t* b) {
    asm volatile(
        "mma.sync.aligned.m16n8k16.row.col.f32.f16.f16.f32 "
        "{%0,%1,%2,%3},{%4,%5,%6,%7},{%8,%9},{%0,%1,%2,%3};"
        : "+f"(c[0]), "+f"(c[1]), "+f"(c[2]), "+f"(c[3])
        : "r"(a[0]), "r"(a[1]), "r"(a[2]), "r"(a[3]), "r"(b[0]), "r"(b[1]));
}

// ---------------- normalize memory + zero scratch (launch 0) ----------------
__global__ void k_norm_mem(const float* __restrict__ mem) {
    int i = blockIdx.x;
    int t = threadIdx.x;
    __shared__ float red[256];
    const float* r = mem + (size_t)i * Hdim;
    float v0 = r[t];
    float v1 = r[t + 256];
    red[t] = v0 * v0 + v1 * v1;
    __syncthreads();
    for (int s = 128; s > 0; s >>= 1) {
        if (t < s) red[t] += red[t + s];
        __syncthreads();
    }
    float inv = 1.0f / fmaxf(sqrtf(red[0]), 1e-12f);
    float n0 = v0 * inv, n1 = v1 * inv;
    size_t b = (size_t)i * Hdim + t;
    g_mn[b] = n0; g_mn[b + 256] = n1;
    g_mh[b] = __float2half_rn(n0);
    g_mh[b + 256] = __float2half_rn(n1);
    // fold in scratch zeroing (Ndim blocks x 16 rows = Bdim)
    if (t < 16) {
        int j = i * 16 + t;
        g_rowsum[j] = 0.0f;
        g_rowmax[j] = 0ull;
    } else if (t == 16) {
        g_colmax[i] = 0u;
        g_cnt[i] = 0u;
    }
}

// ---------------- normalize z (warp per row) (launch 1) ----------------
__global__ void k_zsplit(const float* __restrict__ z) {
    int row = blockIdx.x * 8 + (threadIdx.x >> 5);
    int lane = threadIdx.x & 31;
    const float4* zr = (const float4*)(z + (size_t)row * Hdim);
    float4 v[4];
    float ss = 0.0f;
#pragma unroll
    for (int q = 0; q < 4; q++) {
        v[q] = zr[q * 32 + lane];
        ss += v[q].x * v[q].x + v[q].y * v[q].y + v[q].z * v[q].z + v[q].w * v[q].w;
    }
#pragma unroll
    for (int o = 16; o; o >>= 1) ss += __shfl_xor_sync(0xffffffffu, ss, o);
    float inv = 1.0f / fmaxf(sqrtf(ss), 1e-12f);
    if (lane == 0) g_zinv[row] = inv;
    uint2* zo = (uint2*)(g_zh + (size_t)row * Hdim);
#pragma unroll
    for (int q = 0; q < 4; q++) {
        uint2 p;
        p.x = pkh(__float2half_rn(v[q].x * inv), __float2half_rn(v[q].y * inv));
        p.y = pkh(__float2half_rn(v[q].z * inv), __float2half_rn(v[q].w * inv));
        zo[q * 32 + lane] = p;
    }
}

// ---------------- transpose raw mem -> memT fp16 (launch 2) ----------------
__global__ void k_memT(const float* __restrict__ mem) {
    __shared__ float t[32][33];
    int h0 = blockIdx.x * 32, n0 = blockIdx.y * 32;
    int tx = threadIdx.x, ty = threadIdx.y;
#pragma unroll
    for (int i = 0; i < 4; i++)
        t[ty + 8 * i][tx] = mem[(size_t)(n0 + ty + 8 * i) * Hdim + h0 + tx];
    __syncthreads();
#pragma unroll
    for (int i = 0; i < 4; i++) {
        int h = h0 + ty + 8 * i, n = n0 + tx;
        g_mth[(size_t)h * Ndim + n] = __float2half_rn(t[tx][ty + 8 * i]);
    }
}

// ---------------- mma.sync GEMM (128x128 block, BK=64, 3-stage, 2 CTAs/SM) ----------------
// PHASE 1: sim = zh @ mh^T -> exp, Wh, rowsum, rowmax
// PHASE 2: zhat = Wh @ mth^T / rowsum -> out
template <int KTOT, int PHASE>
__global__ __launch_bounds__(256, 2)
void k_gemm_mma(float* __restrict__ out) {
    constexpr int NC = KTOT / 64;
    constexpr int STAGE = 2 * 16384;          // A(16KB)+B(16KB)
    extern __shared__ __align__(128) char smraw[];
    const uint32_t smb = smem_u32(smraw);

    const int tid = threadIdx.x;
    const int lane = tid & 31;
    const int w = tid >> 5;
    const int wm = (w & 3) << 5;              // warp row base (0..96)
    const int wn = (w >> 2) << 6;             // warp col base (0/64)
    const int m0 = blockIdx.y << 7;
    const int n0 = blockIdx.x << 7;

    const __half *Ah, *Bh;
    if (PHASE == 1) { Ah = g_zh; Bh = g_mh;  }
    else            { Ah = g_Wh; Bh = g_mth; }

    // cp.async granule mapping: 4 per operand per thread (128 rows x 128B)
    int grow[4], gcol[4], gswo[4];
#pragma unroll
    for (int q = 0; q < 4; q++) {
        int id = tid + (q << 8);
        grow[q] = id >> 3;
        gcol[q] = (id & 7) << 3;
        gswo[q] = grow[q] * 128 + (((id & 7) ^ (grow[q] & 7)) << 4);
    }

    float acc[2][8][4];
#pragma unroll
    for (int i = 0; i < 2; i++)
#pragma unroll
        for (int j = 0; j < 8; j++)
#pragma unroll
            for (int q = 0; q < 4; q++) acc[i][j][q] = 0.0f;

#define LOAD_STAGE(c, s) do {                                                        \
    uint32_t sb_ = smb + (s) * STAGE;                                                \
    size_t k0_ = (size_t)((c) << 6);                                                 \
    _Pragma("unroll")                                                                \
    for (int q = 0; q < 4; q++) {                                                    \
        size_t ao_ = (size_t)(m0 + grow[q]) * KTOT + k0_ + gcol[q];                  \
        size_t bo_ = (size_t)(n0 + grow[q]) * KTOT + k0_ + gcol[q];                  \
        cp16(sb_ + gswo[q],         Ah + ao_);                                       \
        cp16(sb_ + 16384 + gswo[q], Bh + bo_);                                       \
    }                                                                                \
    CP_COMMIT();                                                                     \
} while (0)

    LOAD_STAGE(0, 0);
    LOAD_STAGE(1, 1);

    int st = 0;
    for (int c = 0; c < NC; c++) {
        int pf = c + 2;
        int pst = st + 2; if (pst >= 3) pst -= 3;
        if (pf < NC) { LOAD_STAGE(pf, pst); } else { CP_COMMIT(); }
        CP_WAIT(2);
        __syncthreads();

        const uint32_t sA = smb + st * STAGE;
        const uint32_t sB = sA + 16384;

#pragma unroll
        for (int k16 = 0; k16 < 4; k16++) {
            uint32_t ah[2][4];
#pragma unroll
            for (int mi = 0; mi < 2; mi++) {
                int rA = wm + (mi << 4) + (lane & 15);
                int cA = (k16 << 1) + (lane >> 4);
                uint32_t off = rA * 128 + ((cA ^ (rA & 7)) << 4);
                ldsm4(ah[mi], sA + off);
            }
            uint32_t bh[4][4];
#pragma unroll
            for (int ng = 0; ng < 4; ng++) {
                int rB = wn + (ng << 4) + (lane & 7) + ((lane & 16) >> 1);
                int cB = (k16 << 1) + ((lane >> 3) & 1);
                uint32_t off = rB * 128 + ((cB ^ (rB & 7)) << 4);
                ldsm4(bh[ng], sB + off);
            }
#pragma unroll
            for (int mi = 0; mi < 2; mi++)
#pragma unroll
                for (int ng = 0; ng < 4; ng++)
#pragma unroll
                    for (int s2 = 0; s2 < 2; s2++)
                        mma16816(acc[mi][ng * 2 + s2], ah[mi], &bh[ng][s2 * 2]);
        }
        __syncthreads();
        st = st + 1 == 3 ? 0 : st + 1;
    }
#undef LOAD_STAGE

    // ---------------- epilogue ----------------
    const int rq = lane >> 2;
    const int cq = (lane & 3) << 1;

    if (PHASE == 1) {
        float rs[2][2] = {{0.f, 0.f}, {0.f, 0.f}};
        float bv[2][2] = {{-1e30f, -1e30f}, {-1e30f, -1e30f}};
        int   bi[2][2] = {{0, 0}, {0, 0}};
#pragma unroll
        for (int mi = 0; mi < 2; mi++)
#pragma unroll
            for (int ni = 0; ni < 8; ni++) {
                float* cc = acc[mi][ni];
                int colb = n0 + wn + ni * 8 + cq;
#pragma unroll
                for (int h = 0; h < 2; h++) {
                    float v0 = cc[h * 2], v1 = cc[h * 2 + 1];
                    float e0 = __expf(v0), e1 = __expf(v1);
                    rs[mi][h] += e0 + e1;
                    if (v0 > bv[mi][h]) { bv[mi][h] = v0; bi[mi][h] = colb; }
                    if (v1 > bv[mi][h]) { bv[mi][h] = v1; bi[mi][h] = colb + 1; }
                    int row = m0 + wm + mi * 16 + rq + h * 8;
                    size_t o = (size_t)row * Ndim + colb;
                    *(uint32_t*)&g_Wh[o] = pkh(__float2half_rn(e0), __float2half_rn(e1));
                }
            }
#pragma unroll
        for (int mi = 0; mi < 2; mi++)
#pragma unroll
            for (int h = 0; h < 2; h++) {
#pragma unroll
                for (int o = 1; o <= 2; o <<= 1) {
                    rs[mi][h] += __shfl_xor_sync(0xffffffffu, rs[mi][h], o);
                    float ov = __shfl_xor_sync(0xffffffffu, bv[mi][h], o);
                    int   oi = __shfl_xor_sync(0xffffffffu, bi[mi][h], o);
                    if (ov > bv[mi][h]) { bv[mi][h] = ov; bi[mi][h] = oi; }
                }
                if ((lane & 3) == 0) {
                    int row = m0 + wm + mi * 16 + rq + h * 8;
                    atomicAdd(&g_rowsum[row], rs[mi][h]);
                    unsigned long long key =
                        ((unsigned long long)keyenc(bv[mi][h]) << 32) | (unsigned int)bi[mi][h];
                    atomicMax(&g_rowmax[row], key);
                }
            }
    } else {
#pragma unroll
        for (int mi = 0; mi < 2; mi++)
#pragma unroll
            for (int h = 0; h < 2; h++) {
                int row = m0 + wm + mi * 16 + rq + h * 8;
                float inv = 1.0f / g_rowsum[row];
#pragma unroll
                for (int ni = 0; ni < 8; ni++) {
                    float* cc = acc[mi][ni];
                    int col = n0 + wn + ni * 8 + cq;
                    float2 v = make_float2(cc[h * 2] * inv, cc[h * 2 + 1] * inv);
                    *(float2*)&out[(size_t)row * Hdim + col] = v;
                }
            }
    }
}

// ---------------- argmax fix + count + colmax (fused) ----------------
__global__ void k_argmax_fix(const float* __restrict__ z) {
    const int wid = threadIdx.x >> 5, lane = threadIdx.x & 31;
    const int row = blockIdx.x * 8 + wid;
    __shared__ int s_cnt[8];
    __shared__ int s_cand[8][16];

    // each lane holds 64 halfs (8 x uint4) of this row's W
    const uint4* wv4 = (const uint4*)(g_Wh + (size_t)row * Ndim);
    uint4 v[8];
#pragma unroll
    for (int t = 0; t < 8; t++) v[t] = wv4[t * 32 + lane];

    float a1 = -1e30f, a2 = -1e30f;
#pragma unroll
    for (int t = 0; t < 8; t++) {
        const unsigned int* pw = (const unsigned int*)&v[t];
#pragma unroll
        for (int u = 0; u < 4; u++) {
            __half2 h2 = *(const __half2*)&pw[u];
            float w0 = __half2float(__low2half(h2));
            float w1 = __half2float(__high2half(h2));
            float mx = fmaxf(w0, w1), mn = fminf(w0, w1);
            if (mx > a1) { a2 = fmaxf(a1, mn); a1 = mx; }
            else { a2 = fmaxf(a2, mx); }
        }
    }
#pragma unroll
    for (int o = 16; o; o >>= 1) {
        float b1 = __shfl_xor_sync(0xffffffffu, a1, o);
        float b2 = __shfl_xor_sync(0xffffffffu, a2, o);
        if (b1 > a1) { a2 = fmaxf(a1, b2); a1 = b1; }
        else if (b1 > a2) { a2 = b1; }
    }

    unsigned long long fkey = g_rowmax[row];
    float thr = a1 * (1.0f - 1e-3f);

    if (a2 >= thr) {
        // gather candidates
        if (lane == 0) s_cnt[wid] = 0;
        __syncwarp();
#pragma unroll
        for (int t = 0; t < 8; t++) {
            const unsigned int* pw = (const unsigned int*)&v[t];
#pragma unroll
            for (int u = 0; u < 4; u++) {
                __half2 h2 = *(const __half2*)&pw[u];
                float w0 = __half2float(__low2half(h2));
                float w1 = __half2float(__high2half(h2));
                int jb = t * 256 + u * 2 + lane * 8;
                if (w0 >= thr) {
                    int p = atomicAdd(&s_cnt[wid], 1);
                    if (p < 16) s_cand[wid][p] = jb;
                }
                if (w1 >= thr) {
                    int p = atomicAdd(&s_cnt[wid], 1);
                    if (p < 16) s_cand[wid][p] = jb + 1;
                }
            }
        }
        __syncwarp();
        int cnt = min(s_cnt[wid], 16);

        float zin = g_zinv[row];
        const float* zr = z + (size_t)row * Hdim;
        float best = -1e30f;
        int bi = -1;
        for (int c = 0; c < cnt; c++) {
            int j = s_cand[wid][c];
            const float* mr = g_mn + (size_t)j * Hdim;
            float s = 0.0f;
            for (int t = 0; t < 16; t++) {
                int h = t * 32 + lane;
                s += zr[h] * zin * mr[h];
            }
#pragma unroll
            for (int o = 16; o; o >>= 1) s += __shfl_down_sync(0xffffffffu, s, o);
            s = __shfl_sync(0xffffffffu, s, 0);
            if (s > best) { best = s; bi = j; }
        }
        fkey = ((unsigned long long)keyenc(best) << 32) | (unsigned int)bi;
        if (lane == 0) g_rowmax[row] = fkey;
    }

    // fused count + colmax on the final key
    if (lane == 0) {
        unsigned int idx = (unsigned int)(fkey & 0xFFFFFFFFull);
        atomicAdd(&g_cnt[idx], 1u);
        atomicMax(&g_colmax[idx], (unsigned int)(fkey >> 32));
    }
}

// ---------------- exclusive prefix scan over 2048 counts (one block) ----------------
__global__ void k_prefix() {
    __shared__ unsigned int sa[Ndim], sb[Ndim];
    int t = threadIdx.x;
    sa[t] = g_cnt[t]; sa[t + 1024] = g_cnt[t + 1024];
    __syncthreads();
    unsigned int* src = sa;
    unsigned int* dst = sb;
    for (int d = 1; d < Ndim; d <<= 1) {
#pragma unroll
        for (int q = 0; q < 2; q++) {
            int i = t + q * 1024;
            dst[i] = src[i] + (i >= d ? src[i - d] : 0u);
        }
        __syncthreads();
        unsigned int* tmp = src; src = dst; dst = tmp;
    }
#pragma unroll
    for (int q = 0; q < 2; q++) {
        int i = t + q * 1024;
        unsigned int excl = src[i] - g_cnt[i];
        g_off[i] = excl;
        g_cur[i] = excl;
    }
}

// ---------------- fill row list ----------------
__global__ void k_fill() {
    int b = blockIdx.x * blockDim.x + threadIdx.x;
    if (b >= Bdim) return;
    unsigned int idx = (unsigned int)(g_rowmax[b] & 0xFFFFFFFFull);
    unsigned int pos = atomicAdd(&g_cur[idx], 1u);
    g_rowlist[pos] = (unsigned int)b;
}

// ---------------- per-slot update + finalize (no atomics) ----------------
__global__ void k_update(const float* __restrict__ z, const float* __restrict__ mem,
                         float* __restrict__ out) {
    int n = blockIdx.x;
    int t = threadIdx.x;
    const float* mr = mem + (size_t)n * Hdim;
    float* o = out + (size_t)Bdim * Hdim + (size_t)n * Hdim;
    int cnt = (int)g_cnt[n];
    if (cnt == 0) {
        o[t] = mr[t];
        o[t + 256] = mr[t + 256];
        return;
    }
    float cm = keydec(g_colmax[n]);
    int off = (int)g_off[n];
    float a0 = 0.0f, a1 = 0.0f, denom = 0.0f;
    for (int r = 0; r < cnt; r++) {
        int row = (int)g_rowlist[off + r];
        unsigned long long key = g_rowmax[row];
        float val = keydec((unsigned int)(key >> 32));
        float p = __expf(val - cm);
        denom += p;
        const float* zr = z + (size_t)row * Hdim;
        a0 += p * zr[t];
        a1 += p * zr[t + 256];
    }
    float invd = 1.0f / denom;
    float v0 = mr[t] + a0 * invd;
    float v1 = mr[t + 256] + a1 * invd;
    __shared__ float red[256];
    red[t] = v0 * v0 + v1 * v1;
    __syncthreads();
    for (int s = 128; s > 0; s >>= 1) {
        if (t < s) red[t] += red[t + s];
        __syncthreads();
    }
    float inv = 1.0f / fmaxf(sqrtf(red[0]), 1e-12f);
    o[t] = v0 * inv;
    o[t + 256] = v1 * inv;
}

// ---------------- launch ----------------
extern "C" void kernel_launch(void* const* d_in, const int* in_sizes, int n_in,
                              void* d_out, int out_size) {
    (void)in_sizes; (void)n_in; (void)out_size;
    const float* z   = (const float*)d_in[0];
    const float* mem = (const float*)d_in[1];
    float* out = (float*)d_out;

    const int DS = 3 * 2 * 16384;   // 96KB
    cudaFuncSetAttribute(k_gemm_mma<Hdim, 1>, cudaFuncAttributeMaxDynamicSharedMemorySize, DS);
    cudaFuncSetAttribute(k_gemm_mma<Ndim, 2>, cudaFuncAttributeMaxDynamicSharedMemorySize, DS);

    k_norm_mem<<<Ndim, 256>>>(mem);                                    // 0
    k_zsplit<<<Bdim / 8, 256>>>(z);                                    // 1
    k_memT<<<dim3(Hdim / 32, Ndim / 32), dim3(32, 8)>>>(mem);          // 2
    k_gemm_mma<Hdim, 1><<<dim3(Ndim / 128, Bdim / 128), 256, DS>>>(nullptr);  // 3 (ncu slot)
    k_argmax_fix<<<Bdim / 8, 256>>>(z);                                // 4
    k_prefix<<<1, 1024>>>();                                           // 5
    k_fill<<<Bdim / 256, 256>>>();                                     // 6
    k_gemm_mma<Ndim, 2><<<dim3(Hdim / 128, Bdim / 128), 256, DS>>>(out);      // 7
    k_update<<<Ndim, 256>>>(z, mem, out);                              // 8
}